// round 14
// baseline (speedup 1.0000x reference)
#include <cuda_runtime.h>
#include <cuda_bf16.h>
#include <cuda_fp16.h>
#include <cstdint>

typedef __nv_bfloat16 bf16;

#define Bz   32
#define Sz   128
#define Tz   127
#define Vz   32000
#define Ez   512
#define Gz   1024
#define HIz  512
#define G4z  4096
#define MR   4064   /* Tz*Bz */

// ------------------------- static device scratch -------------------------
__device__ __half g_Woutf[(size_t)Vz*Gz];           // fp16 hi of W_out
__device__ bf16  g_Wih_hi[(size_t)G4z*Ez];
__device__ bf16  g_Wih_lo[(size_t)G4z*Ez];
__device__ bf16  g_Whh_hi[(size_t)G4z*Gz];
__device__ bf16  g_Whh_lo[(size_t)G4z*Gz];
__device__ bf16  g_H_hi[(size_t)(Tz+2)*Bz*Gz];      // bf16 h for recurrence
__device__ bf16  g_H_lo[(size_t)(Tz+2)*Bz*Gz];
__device__ __half g_Hf_hi[(size_t)(Tz+2)*Bz*Gz];    // fp16 h for logits
__device__ bf16  g_X_hi[(size_t)MR*Ez];
__device__ bf16  g_X_lo[(size_t)MR*Ez];
__device__ float g_Xg[(size_t)MR*G4z];
__device__ float g_c[Bz*Gz];
__device__ float g_Q[Bz*HIz];
__device__ float g_Kb[Bz*16*HIz];
__device__ float g_Vb[Bz*16*HIz];
__device__ float g_ctx[Bz*HIz];
__device__ float g_att[Bz*HIz];
__device__ float g_ff[Bz*3*HIz];
__device__ float g_ie[Bz*Ez];
__device__ float g_g0[Bz*G4z];
__device__ float g_bsum[G4z];
// prologue split buffers (bf16 hi/lo)
__device__ bf16 g_ent_h[Bz*HIz],   g_ent_l[Bz*HIz];
__device__ bf16 g_nei_h[Bz*16*HIz],g_nei_l[Bz*16*HIz];
__device__ bf16 g_ctx_h[Bz*HIz],   g_ctx_l[Bz*HIz];
__device__ bf16 g_ffs_h[Bz*3*HIz], g_ffs_l[Bz*3*HIz];
__device__ bf16 g_ie_h[Bz*Ez],     g_ie_l[Bz*Ez];
__device__ bf16 g_Wq_h[HIz*HIz],   g_Wq_l[HIz*HIz];
__device__ bf16 g_Wk_h[HIz*HIz],   g_Wk_l[HIz*HIz];
__device__ bf16 g_Wv_h[HIz*HIz],   g_Wv_l[HIz*HIz];
__device__ bf16 g_Wo_h[HIz*HIz],   g_Wo_l[HIz*HIz];
__device__ bf16 g_Wim_h[Ez*3*HIz], g_Wim_l[Ez*3*HIz];

// ------------------------------ helpers ----------------------------------
__device__ __forceinline__ float sigf(float x){ return 1.0f/(1.0f+expf(-x)); }

__device__ __forceinline__ uint32_t smem_u32(const void* p){
    return (uint32_t)__cvta_generic_to_shared(p);
}
__device__ __forceinline__ void ldsmx4(uint32_t* r, const void* p){
    uint32_t a = smem_u32(p);
    asm volatile("ldmatrix.sync.aligned.m8n8.x4.shared.b16 {%0,%1,%2,%3},[%4];\n"
                 : "=r"(r[0]),"=r"(r[1]),"=r"(r[2]),"=r"(r[3]) : "r"(a));
}
__device__ __forceinline__ void ldsmx2(uint32_t* r, const void* p){
    uint32_t a = smem_u32(p);
    asm volatile("ldmatrix.sync.aligned.m8n8.x2.shared.b16 {%0,%1},[%2];\n"
                 : "=r"(r[0]),"=r"(r[1]) : "r"(a));
}
__device__ __forceinline__ void mma_bf(float* d, const uint32_t* a, const uint32_t* b){
    asm volatile("mma.sync.aligned.m16n8k16.row.col.f32.bf16.bf16.f32 "
                 "{%0,%1,%2,%3},{%4,%5,%6,%7},{%8,%9},{%0,%1,%2,%3};\n"
                 : "+f"(d[0]),"+f"(d[1]),"+f"(d[2]),"+f"(d[3])
                 : "r"(a[0]),"r"(a[1]),"r"(a[2]),"r"(a[3]),
                   "r"(b[0]),"r"(b[1]));
}
__device__ __forceinline__ void mma_fp(float* d, const uint32_t* a, const uint32_t* b){
    asm volatile("mma.sync.aligned.m16n8k16.row.col.f32.f16.f16.f32 "
                 "{%0,%1,%2,%3},{%4,%5,%6,%7},{%8,%9},{%0,%1,%2,%3};\n"
                 : "+f"(d[0]),"+f"(d[1]),"+f"(d[2]),"+f"(d[3])
                 : "r"(a[0]),"r"(a[1]),"r"(a[2]),"r"(a[3]),
                   "r"(b[0]),"r"(b[1]));
}
#define CP_ASYNC16P(dst, src, pv) \
    asm volatile("cp.async.cg.shared.global [%0], [%1], 16, %2;" \
                 :: "r"(dst), "l"(src), "r"(pv))
#define CP_ASYNC16(dst, src) \
    asm volatile("cp.async.cg.shared.global [%0], [%1], 16;" :: "r"(dst), "l"(src))
#define CP_COMMIT()  asm volatile("cp.async.commit_group;" ::: "memory")

// --------------------------- prep kernels --------------------------------
__global__ void k_split(const float* __restrict__ src, bf16* __restrict__ hi,
                        bf16* __restrict__ lo, int n){
    int i = blockIdx.x*blockDim.x + threadIdx.x;
    if (i < n){
        float x = src[i];
        bf16 h = __float2bfloat16(x);
        hi[i] = h;
        lo[i] = __float2bfloat16(x - __bfloat162float(h));
    }
}
__global__ void k_half(const float* __restrict__ src, __half* __restrict__ dst, int n){
    int i = blockIdx.x*blockDim.x + threadIdx.x;
    if (i < n) dst[i] = __float2half(src[i]);
}
__global__ void k_bsum(const float* __restrict__ a, const float* __restrict__ b){
    int i = blockIdx.x*blockDim.x + threadIdx.x;
    if (i < G4z) g_bsum[i] = a[i] + b[i];
}
__global__ void k_xgather(const float* __restrict__ emb, const int* __restrict__ sent){
    int i = blockIdx.x*blockDim.x + threadIdx.x;
    if (i < MR*Ez){
        int r = i >> 9, col = i & 511;
        int t = r >> 5, b = r & 31;
        int idx = sent[b*Sz + t];
        float v = emb[(size_t)idx*Ez + col];
        bf16 h = __float2bfloat16(v);
        g_X_hi[i] = h;
        g_X_lo[i] = __float2bfloat16(v - __bfloat162float(h));
    }
}
__global__ void k_ff(const float* __restrict__ ent, const float* __restrict__ img){
    int i = blockIdx.x*blockDim.x + threadIdx.x;
    if (i < Bz*HIz){
        int b = i >> 9, j = i & 511;
        float* row = g_ff + (size_t)b*3*HIz;
        row[j]          = ent[i];
        row[HIz + j]    = g_att[i];
        row[2*HIz + j]  = img[i];
    }
}

// ------------------------------ attention --------------------------------
__global__ void k_attn(const int* __restrict__ nnum){
    int bh = blockIdx.x;
    int b = bh >> 3, h = bh & 7;
    int d = threadIdx.x;                    // 64 threads
    __shared__ float red[64];
    __shared__ float sc[16];
    float q = g_Q[b*HIz + h*64 + d];
    for (int n = 0; n < 16; n++){
        red[d] = q * g_Kb[(size_t)(b*16+n)*HIz + h*64 + d];
        __syncthreads();
        for (int o = 32; o; o >>= 1){
            if (d < o) red[d] += red[d+o];
            __syncthreads();
        }
        if (d == 0) sc[n] = red[0]*0.125f;
        __syncthreads();
    }
    int num = nnum[b];
    float a[16], mx = -1e30f;
#pragma unroll
    for (int n = 0; n < 16; n++){
        a[n] = (n >= num) ? -1e9f : sc[n];
        mx = fmaxf(mx, a[n]);
    }
    float ssum = 0.f;
#pragma unroll
    for (int n = 0; n < 16; n++){ a[n] = expf(a[n]-mx); ssum += a[n]; }
    float inv = 1.f/ssum;
    float ctx = 0.f;
#pragma unroll
    for (int n = 0; n < 16; n++)
        ctx += a[n] * g_Vb[(size_t)(b*16+n)*HIz + h*64 + d];
    g_ctx[b*HIz + h*64 + d] = ctx*inv;
}

// --------------------------- first LSTM step -----------------------------
__global__ void k_step0(){
    int i = blockIdx.x*blockDim.x + threadIdx.x;
    if (i < Bz*Gz){
        int b = i >> 10, j = i & 1023;
        const float* g0 = g_g0 + (size_t)b*G4z;
        float gi = g0[j], gg = g0[j+2*Gz], go = g0[j+3*Gz];
        float c = sigf(gi)*tanhf(gg);
        float h = sigf(go)*tanhf(c);
        g_c[i] = c;
        bf16 hh = __float2bfloat16(h);
        g_H_hi[i] = hh;
        g_H_lo[i] = __float2bfloat16(h - __bfloat162float(hh));
    }
}

// ---- fused recurrence step: 128 blocks x 128 thr, cp.async 3-stage ------
// Block nb owns gate cols {nb*8..+7} across all 4 quadrants (warp=quadrant).
#define SLD2 72
#define STEP_MAT (32*SLD2*2)     /* 4608 B per 32x64 bf16 matrix */
#define STEP_STG (4*STEP_MAT)    /* Ahi,Alo,Bhi,Blo = 18432 */
#define STEP_SMEM (3*STEP_STG)   /* 55296 */
__global__ void __launch_bounds__(128, 1) k_step(int s){
    extern __shared__ char dsm[];
    __shared__ float sG[4][32][8];
    const uint32_t sb = smem_u32(dsm);
    const int tid = threadIdx.x, warp = tid >> 5, lane = tid & 31;
    const int nb = blockIdx.x, c0 = nb*8;
    const bf16* hHi = g_H_hi + (size_t)s*Bz*Gz;
    const bf16* hLo = g_H_lo + (size_t)s*Bz*Gz;

    float acc[2][4];
#pragma unroll
    for (int a=0;a<2;a++)
#pragma unroll
    for (int c=0;c<4;c++) acc[a][c]=0.f;

    auto load_stage = [&](int ch, int buf){
        const int kk = ch*64;
        const uint32_t s0 = sb + buf*STEP_STG;
#pragma unroll
        for (int i = 0; i < 2; i++){
            int u = tid + i*128;
            int r = u >> 3, c = (u & 7)*8;
            uint32_t so = (uint32_t)((r*SLD2 + c)*2);
            CP_ASYNC16(s0 + so,              hHi + (size_t)r*Gz + kk + c);
            CP_ASYNC16(s0 + STEP_MAT + so,   hLo + (size_t)r*Gz + kk + c);
            int g = (r >> 3)*Gz + c0 + (r & 7);
            CP_ASYNC16(s0 + 2*STEP_MAT + so, g_Whh_hi + (size_t)g*Gz + kk + c);
            CP_ASYNC16(s0 + 3*STEP_MAT + so, g_Whh_lo + (size_t)g*Gz + kk + c);
        }
    };
    load_stage(0, 0); CP_COMMIT();
    load_stage(1, 1); CP_COMMIT();

    for (int ch = 0; ch < 16; ch++){
        asm volatile("cp.async.wait_group 1;" ::: "memory");
        __syncthreads();
        if (ch + 2 < 16) load_stage(ch + 2, (ch + 2) % 3);
        CP_COMMIT();
        const char* st = dsm + (ch % 3)*STEP_STG;
        const bf16* pA0 = (const bf16*)(st);
        const bf16* pA1 = (const bf16*)(st + STEP_MAT);
        const bf16* pB0 = (const bf16*)(st + 2*STEP_MAT);
        const bf16* pB1 = (const bf16*)(st + 3*STEP_MAT);
#pragma unroll
        for (int ks = 0; ks < 64; ks += 16){
            uint32_t ah[2][4], al[2][4], bh[2], bl[2];
#pragma unroll
            for (int mi = 0; mi < 2; mi++){
                int row = mi*16 + (lane & 15);
                int kc  = ks + (lane >> 4)*8;
                ldsmx4(ah[mi], pA0 + row*SLD2 + kc);
                ldsmx4(al[mi], pA1 + row*SLD2 + kc);
            }
            {
                int l = lane & 15;
                int row = warp*8 + (l & 7);
                int kc  = ks + ((l >> 3) & 1)*8;
                ldsmx2(bh, pB0 + row*SLD2 + kc);
                ldsmx2(bl, pB1 + row*SLD2 + kc);
            }
#pragma unroll
            for (int mi = 0; mi < 2; mi++){
                mma_bf(acc[mi], ah[mi], bh);
                mma_bf(acc[mi], ah[mi], bl);
                mma_bf(acc[mi], al[mi], bh);
            }
        }
    }
    // scatter: warp q holds quadrant q for (b, jl)
#pragma unroll
    for (int mi = 0; mi < 2; mi++)
#pragma unroll
    for (int h = 0; h < 2; h++){
        int b  = mi*16 + (lane >> 2) + h*8;
        int jl = (lane & 3)*2;
        sG[warp][b][jl]   = acc[mi][h*2];
        sG[warp][b][jl+1] = acc[mi][h*2+1];
    }
    __syncthreads();
    // LSTM cell update: 32x8 elements
    bf16* oHi = g_H_hi + (size_t)(s+1)*Bz*Gz;
    bf16* oLo = g_H_lo + (size_t)(s+1)*Bz*Gz;
    __half* fHi = g_Hf_hi + (size_t)(s+1)*Bz*Gz;
    const float* Xg = g_Xg + (size_t)s*Bz*G4z;
    for (int e = tid; e < 256; e += 128){
        int b = e >> 3, jl = e & 7;
        int col = c0 + jl;
        const float* xg = Xg + (size_t)b*G4z;
        float gi = sG[0][b][jl] + xg[col];
        float gf = sG[1][b][jl] + xg[col +   Gz];
        float gg = sG[2][b][jl] + xg[col + 2*Gz];
        float go = sG[3][b][jl] + xg[col + 3*Gz];
        float c = sigf(gf)*g_c[b*Gz+col] + sigf(gi)*tanhf(gg);
        float h = sigf(go)*tanhf(c);
        g_c[b*Gz+col] = c;
        bf16 hb = __float2bfloat16(h);
        oHi[b*Gz+col] = hb;
        oLo[b*Gz+col] = __float2bfloat16(h - __bfloat162float(hb));
        fHi[b*Gz+col] = __float2half(h);
    }
}

// ------ pipelined split-bf16 3-term GEMM (Xg + prologue), act 0/1=tanh ---
#define LDT   40
#define MATB  (128*LDT*2)
#define STGB  (4*MATB)
#define GEMM_SMEM (3*STGB)       /* 122880 */
__global__ void __launch_bounds__(256, 1) k_gemm3p(
    const bf16* __restrict__ Ahi, const bf16* __restrict__ Alo,
    const bf16* __restrict__ Bhi, const bf16* __restrict__ Blo,
    const float* __restrict__ bias, float* __restrict__ out,
    int M, int N, int K, int act)
{
    extern __shared__ char smem[];
    const uint32_t sb = smem_u32(smem);
    const int tid = threadIdx.x, warp = tid >> 5, lane = tid & 31;
    const int m0 = blockIdx.x*128, n0 = blockIdx.y*128;
    const int wm = (warp >> 2)*64, wn = (warp & 3)*32;
    const int NC = K >> 5;

    float acc[4][4][4];
#pragma unroll
    for (int a=0;a<4;a++)
#pragma unroll
    for (int b=0;b<4;b++)
#pragma unroll
    for (int c=0;c<4;c++) acc[a][b][c]=0.f;

    auto load_stage = [&](int chunk, int buf){
        const int kk = chunk << 5;
        const uint32_t s0 = sb + buf*STGB;
#pragma unroll
        for (int i = 0; i < 2; i++){
            int u = tid + i*256;
            int r = u >> 2, c = (u & 3)*8;
            uint32_t so = (uint32_t)((r*LDT + c)*2);
            int gr = m0 + r;
            uint32_t pv = (gr < M) ? 16u : 0u;
            int grc = gr < M ? gr : (M-1);
            CP_ASYNC16P(s0 + so,          Ahi + (size_t)grc*K + kk + c, pv);
            CP_ASYNC16P(s0 + MATB + so,   Alo + (size_t)grc*K + kk + c, pv);
            int gn = n0 + r;
            CP_ASYNC16(s0 + 2*MATB + so,  Bhi + (size_t)gn*K + kk + c);
            CP_ASYNC16(s0 + 3*MATB + so,  Blo + (size_t)gn*K + kk + c);
        }
    };
    load_stage(0, 0); CP_COMMIT();
    if (NC > 1){ load_stage(1, 1); } CP_COMMIT();

    for (int c = 0; c < NC; c++){
        asm volatile("cp.async.wait_group 1;" ::: "memory");
        __syncthreads();
        if (c + 2 < NC) load_stage(c + 2, (c + 2) % 3);
        CP_COMMIT();
        const char* st = smem + (c % 3)*STGB;
        const bf16* pA0 = (const bf16*)(st);
        const bf16* pA1 = (const bf16*)(st + MATB);
        const bf16* pB0 = (const bf16*)(st + 2*MATB);
        const bf16* pB1 = (const bf16*)(st + 3*MATB);
#pragma unroll
        for (int ks = 0; ks < 32; ks += 16){
            uint32_t ah[4][4], al[4][4], bh[2][4], bl[2][4];
#pragma unroll
            for (int mi = 0; mi < 4; mi++){
                int row = wm + mi*16 + (lane & 15);
                int kc  = ks + (lane >> 4)*8;
                ldsmx4(ah[mi], pA0 + row*LDT + kc);
                ldsmx4(al[mi], pA1 + row*LDT + kc);
            }
#pragma unroll
            for (int ni = 0; ni < 2; ni++){
                int j = lane >> 3;
                int row = wn + ni*16 + ((j >> 1)*8) + (lane & 7);
                int kc  = ks + (j & 1)*8;
                ldsmx4(bh[ni], pB0 + row*LDT + kc);
                ldsmx4(bl[ni], pB1 + row*LDT + kc);
            }
#pragma unroll
            for (int mi = 0; mi < 4; mi++)
#pragma unroll
                for (int nj = 0; nj < 4; nj++){
                    const uint32_t* fh = &bh[nj >> 1][(nj & 1)*2];
                    const uint32_t* fl = &bl[nj >> 1][(nj & 1)*2];
                    mma_bf(acc[mi][nj], ah[mi], fh);
                    mma_bf(acc[mi][nj], ah[mi], fl);
                    mma_bf(acc[mi][nj], al[mi], fh);
                }
        }
    }
#pragma unroll
    for (int mi = 0; mi < 4; mi++)
#pragma unroll
    for (int nj = 0; nj < 4; nj++){
        int n = n0 + wn + nj*8 + (lane & 3)*2;
        float b0 = bias[n], b1 = bias[n+1];
#pragma unroll
        for (int h = 0; h < 2; h++){
            int m = m0 + wm + mi*16 + (lane >> 2) + h*8;
            if (m < M){
                float v0 = acc[mi][nj][h*2]   + b0;
                float v1 = acc[mi][nj][h*2+1] + b1;
                if (act == 1){ v0 = tanhf(v0); v1 = tanhf(v1); }
                out[(size_t)m*N + n]   = v0;
                out[(size_t)m*N + n+1] = v1;
            }
        }
    }
}

// ---- logits: fp16 1-term pipelined GEMM, D = Ah @ Bh^T + bias -----------
// remap: row m = t*32+b  ->  out[(b*127+t)*Vz + n]; mt0 = M-tile offset
#define MATB2 (128*LDT*2)        /* 10240 */
#define STGB2 (2*MATB2)          /* Ah, Bh */
#define LOG_SMEM (3*STGB2)       /* 61440 */
__global__ void __launch_bounds__(256, 1) k_logits16(
    const __half* __restrict__ Ahi,
    const __half* __restrict__ Bhi,
    const float* __restrict__ bias, float* __restrict__ out,
    int M, int N, int K, int mt0)
{
    extern __shared__ char smem[];
    const uint32_t sb = smem_u32(smem);
    const int tid = threadIdx.x, warp = tid >> 5, lane = tid & 31;
    const int m0 = (blockIdx.x + mt0)*128, n0 = blockIdx.y*128;
    const int wm = (warp >> 2)*64, wn = (warp & 3)*32;
    const int NC = K >> 5;

    float acc[4][4][4];
#pragma unroll
    for (int a=0;a<4;a++)
#pragma unroll
    for (int b=0;b<4;b++)
#pragma unroll
    for (int c=0;c<4;c++) acc[a][b][c]=0.f;

    auto load_stage = [&](int chunk, int buf){
        const int kk = chunk << 5;
        const uint32_t s0 = sb + buf*STGB2;
#pragma unroll
        for (int i = 0; i < 2; i++){
            int u = tid + i*256;
            int r = u >> 2, c = (u & 3)*8;
            uint32_t so = (uint32_t)((r*LDT + c)*2);
            int gr = m0 + r;
            uint32_t pv = (gr < M) ? 16u : 0u;
            int grc = gr < M ? gr : (M-1);
            CP_ASYNC16P(s0 + so,          Ahi + (size_t)grc*K + kk + c, pv);
            int gn = n0 + r;
            CP_ASYNC16(s0 + MATB2 + so,   Bhi + (size_t)gn*K + kk + c);
        }
    };
    load_stage(0, 0); CP_COMMIT();
    load_stage(1, 1); CP_COMMIT();

    for (int c = 0; c < NC; c++){
        asm volatile("cp.async.wait_group 1;" ::: "memory");
        __syncthreads();
        if (c + 2 < NC) load_stage(c + 2, (c + 2) % 3);
        CP_COMMIT();
        const char* st = smem + (c % 3)*STGB2;
        const __half* pA0 = (const __half*)(st);
        const __half* pB0 = (const __half*)(st + MATB2);
#pragma unroll
        for (int ks = 0; ks < 32; ks += 16){
            uint32_t ah[4][4], bh[2][4];
#pragma unroll
            for (int mi = 0; mi < 4; mi++){
                int row = wm + mi*16 + (lane & 15);
                int kc  = ks + (lane >> 4)*8;
                ldsmx4(ah[mi], pA0 + row*LDT + kc);
            }
#pragma unroll
            for (int ni = 0; ni < 2; ni++){
                int j = lane >> 3;
                int row = wn + ni*16 + ((j >> 1)*8) + (lane & 7);
                int kc  = ks + (j & 1)*8;
                ldsmx4(bh[ni], pB0 + row*LDT + kc);
            }
#pragma unroll
            for (int mi = 0; mi < 4; mi++)
#pragma unroll
                for (int nj = 0; nj < 4; nj++){
                    const uint32_t* fh = &bh[nj >> 1][(nj & 1)*2];
                    mma_fp(acc[mi][nj], ah[mi], fh);
                }
        }
    }
#pragma unroll
    for (int mi = 0; mi < 4; mi++)
#pragma unroll
    for (int nj = 0; nj < 4; nj++){
        int n = n0 + wn + nj*8 + (lane & 3)*2;
        float b0 = bias[n], b1 = bias[n+1];
#pragma unroll
        for (int h = 0; h < 2; h++){
            int m = m0 + wm + mi*16 + (lane >> 2) + h*8;
            if (m < M){
                int t = m >> 5, b = m & 31;
                size_t off = ((size_t)b*Tz + t)*(size_t)N + n;
                out[off]   = acc[mi][nj][h*2]   + b0;
                out[off+1] = acc[mi][nj][h*2+1] + b1;
            }
        }
    }
}

// ------------------------------- tail ------------------------------------
__global__ void k_tail(const int* __restrict__ sent, const int* __restrict__ slen,
                       float* __restrict__ out, long out_size){
    long base = (long)Bz*Tz*Vz;
    int i = blockIdx.x*blockDim.x + threadIdx.x;
    if (i < Bz*Sz && base + i < out_size)            out[base+i] = (float)sent[i];
    if (i < Bz && base + Bz*Sz + i < out_size)       out[base+Bz*Sz+i] = (float)slen[i];
}

// --------------------- side stream + events (created at load) ------------
struct HxStreams {
    cudaStream_t sB = nullptr;
    cudaEvent_t evF[4] = {nullptr,nullptr,nullptr,nullptr};
    cudaEvent_t evJ = nullptr;
    HxStreams(){
        int lo = 0, hi = 0;
        cudaDeviceGetStreamPriorityRange(&lo, &hi);   // lo = least priority
        if (cudaStreamCreateWithPriority(&sB, cudaStreamNonBlocking, lo) != cudaSuccess){
            sB = nullptr; return;
        }
        bool ok = true;
        for (int i = 0; i < 4; i++)
            ok &= (cudaEventCreateWithFlags(&evF[i], cudaEventDisableTiming) == cudaSuccess);
        ok &= (cudaEventCreateWithFlags(&evJ, cudaEventDisableTiming) == cudaSuccess);
        if (!ok){ sB = nullptr; }
    }
};
static HxStreams g_hx;

// ------------------------------ host side --------------------------------
static inline void* sym(const void* s){ void* p; cudaGetSymbolAddress(&p, s); return p; }

extern "C" void kernel_launch(void* const* d_in, const int* in_sizes, int n_in,
                              void* d_out, int out_size) {
    const float* ent   = (const float*)d_in[0];
    const float* neigh = (const float*)d_in[1];
    const int*   nnum  = (const int*)  d_in[2];
    const float* img   = (const float*)d_in[3];
    const int*   sent  = (const int*)  d_in[4];
    const int*   slen  = (const int*)  d_in[5];
    const float* emb   = (const float*)d_in[6];
    const float* W_ih  = (const float*)d_in[7];
    const float* W_hh  = (const float*)d_in[8];
    const float* b_ih  = (const float*)d_in[9];
    const float* b_hh  = (const float*)d_in[10];
    const float* W_img = (const float*)d_in[11];
    const float* b_img = (const float*)d_in[12];
    const float* W_out = (const float*)d_in[13];
    const float* b_out = (const float*)d_in[14];
    const float* Wq = (const float*)d_in[15]; const float* bq = (const float*)d_in[16];
    const float* Wk = (const float*)d_in[17]; const float* bk = (const float*)d_in[18];
    const float* Wv = (const float*)d_in[19]; const float* bv = (const float*)d_in[20];
    const float* Wo = (const float*)d_in[21]; const float* bo = (const float*)d_in[22];
    float* out = (float*)d_out;

    void *pWoutf = sym(g_Woutf);
    void *pWih_h = sym(g_Wih_hi), *pWih_l = sym(g_Wih_lo);
    void *pHf_h = sym(g_Hf_hi);
    void *pXh = sym(g_X_hi), *pXl = sym(g_X_lo);
    void *pXg = sym(g_Xg), *pBsum = sym(g_bsum);
    void *pQ = sym(g_Q), *pKb = sym(g_Kb), *pVb = sym(g_Vb);
    void *pCtx = sym(g_ctx), *pFf = sym(g_ff);
    void *pIe = sym(g_ie), *pAtt = sym(g_att), *pG0 = sym(g_g0);
    void *pWhh_h = sym(g_Whh_hi), *pWhh_l = sym(g_Whh_lo);
    (void)pWhh_h; (void)pWhh_l;
    void *pEnt_h = sym(g_ent_h), *pEnt_l = sym(g_ent_l);
    void *pNei_h = sym(g_nei_h), *pNei_l = sym(g_nei_l);
    void *pCtx_h = sym(g_ctx_h), *pCtx_l = sym(g_ctx_l);
    void *pFfs_h = sym(g_ffs_h), *pFfs_l = sym(g_ffs_l);
    void *pIe_h = sym(g_ie_h), *pIe_l = sym(g_ie_l);
    void *pWq_h = sym(g_Wq_h), *pWq_l = sym(g_Wq_l);
    void *pWk_h = sym(g_Wk_h), *pWk_l = sym(g_Wk_l);
    void *pWv_h = sym(g_Wv_h), *pWv_l = sym(g_Wv_l);
    void *pWo_h = sym(g_Wo_h), *pWo_l = sym(g_Wo_l);
    void *pWim_h = sym(g_Wim_h), *pWim_l = sym(g_Wim_l);

    cudaFuncSetAttribute(k_gemm3p,  cudaFuncAttributeMaxDynamicSharedMemorySize, GEMM_SMEM);
    cudaFuncSetAttribute(k_logits16,cudaFuncAttributeMaxDynamicSharedMemorySize, LOG_SMEM);
    cudaFuncSetAttribute(k_step,    cudaFuncAttributeMaxDynamicSharedMemorySize, STEP_SMEM);

    // ---- prep: weight conversions, embedding gather ----
    {
        int n = Vz*Gz;
        k_half<<<(n+255)/256, 256>>>(W_out, (__half*)pWoutf, n);
        n = G4z*Ez;
        k_split<<<(n+255)/256, 256>>>(W_ih, (bf16*)pWih_h, (bf16*)pWih_l, n);
        n = G4z*Gz;
        k_split<<<(n+255)/256, 256>>>(W_hh, (bf16*)sym(g_Whh_hi), (bf16*)sym(g_Whh_lo), n);
        k_bsum<<<(G4z+255)/256, 256>>>(b_ih, b_hh);
        n = MR*Ez;
        k_xgather<<<(n+255)/256, 256>>>(emb, sent);
        n = HIz*HIz;
        k_split<<<(n+255)/256, 256>>>(Wq, (bf16*)pWq_h, (bf16*)pWq_l, n);
        k_split<<<(n+255)/256, 256>>>(Wk, (bf16*)pWk_h, (bf16*)pWk_l, n);
        k_split<<<(n+255)/256, 256>>>(Wv, (bf16*)pWv_h, (bf16*)pWv_l, n);
        k_split<<<(n+255)/256, 256>>>(Wo, (bf16*)pWo_h, (bf16*)pWo_l, n);
        n = Ez*3*HIz;
        k_split<<<(n+255)/256, 256>>>(W_img, (bf16*)pWim_h, (bf16*)pWim_l, n);
        n = Bz*HIz;
        k_split<<<(n+255)/256, 256>>>(ent, (bf16*)pEnt_h, (bf16*)pEnt_l, n);
        n = Bz*16*HIz;
        k_split<<<(n+255)/256, 256>>>(neigh, (bf16*)pNei_h, (bf16*)pNei_l, n);
    }

    // ---- prologue: MHA + img_embed + first LSTM step (tensor-core GEMMs) ----
    {
        dim3 g1(1, HIz/128), g4(4, HIz/128);
        k_gemm3p<<<g1, 256, GEMM_SMEM>>>((bf16*)pEnt_h, (bf16*)pEnt_l,
            (bf16*)pWq_h, (bf16*)pWq_l, bq, (float*)pQ, Bz, HIz, HIz, 0);
        k_gemm3p<<<g4, 256, GEMM_SMEM>>>((bf16*)pNei_h, (bf16*)pNei_l,
            (bf16*)pWk_h, (bf16*)pWk_l, bk, (float*)pKb, Bz*16, HIz, HIz, 0);
        k_gemm3p<<<g4, 256, GEMM_SMEM>>>((bf16*)pNei_h, (bf16*)pNei_l,
            (bf16*)pWv_h, (bf16*)pWv_l, bv, (float*)pVb, Bz*16, HIz, HIz, 0);
        k_attn<<<Bz*8, 64>>>(nnum);
        int n = Bz*HIz;
        k_split<<<(n+255)/256, 256>>>((const float*)pCtx, (bf16*)pCtx_h, (bf16*)pCtx_l, n);
        k_gemm3p<<<g1, 256, GEMM_SMEM>>>((bf16*)pCtx_h, (bf16*)pCtx_l,
            (bf16*)pWo_h, (bf16*)pWo_l, bo, (float*)pAtt, Bz, HIz, HIz, 0);
        k_ff<<<(Bz*HIz+255)/256, 256>>>(ent, img);
        n = Bz*3*HIz;
        k_split<<<(n+255)/256, 256>>>((const float*)pFf, (bf16*)pFfs_h, (bf16*)pFfs_l, n);
        k_gemm3p<<<g1, 256, GEMM_SMEM>>>((bf16*)pFfs_h, (bf16*)pFfs_l,
            (bf16*)pWim_h, (bf16*)pWim_l, b_img, (float*)pIe, Bz, HIz, 3*HIz, 1);
        n = Bz*Ez;
        k_split<<<(n+255)/256, 256>>>((const float*)pIe, (bf16*)pIe_h, (bf16*)pIe_l, n);
        dim3 gg(1, G4z/128);
        k_gemm3p<<<gg, 256, GEMM_SMEM>>>((bf16*)pIe_h, (bf16*)pIe_l,
            (bf16*)pWih_h, (bf16*)pWih_l, (const float*)pBsum, (float*)pG0, Bz, G4z, Ez, 0);
        k_step0<<<(Bz*Gz+255)/256, 256>>>();
    }

    // ---- Xg = X @ W_ih^T + bsum for all 127 steps (one GEMM) ----
    {
        dim3 grid((MR+127)/128, G4z/128);
        k_gemm3p<<<grid, 256, GEMM_SMEM>>>((bf16*)pXh, (bf16*)pXl,
                               (bf16*)pWih_h, (bf16*)pWih_l,
                               (const float*)pBsum, (float*)pXg,
                               MR, G4z, Ez, 0);
    }

    const bool fork = (g_hx.sB != nullptr);

    // ---- recurrence: 127 fused steps; fork events every 32 steps ----
    for (int s = 0; s < Tz; s++){
        k_step<<<128, 128, STEP_SMEM>>>(s);
        if (fork){
            if (s == 31)       cudaEventRecord(g_hx.evF[0], 0);
            else if (s == 63)  cudaEventRecord(g_hx.evF[1], 0);
            else if (s == 95)  cudaEventRecord(g_hx.evF[2], 0);
            else if (s == 126) cudaEventRecord(g_hx.evF[3], 0);
        }
    }

    // ---- logits: fp16 1-term [4064,1024]x[1024,32000], remap [B,T,V] ----
    // 4 M-chunks on the side stream, each gated on its last required step.
    if (fork){
        for (int k = 0; k < 4; k++){
            cudaStreamWaitEvent(g_hx.sB, g_hx.evF[k], 0);
            dim3 grid(8, Vz/128);
            k_logits16<<<grid, 256, LOG_SMEM, g_hx.sB>>>(
                (const __half*)pHf_h + Bz*Gz,
                (const __half*)pWoutf, b_out, out, MR, Vz, Gz, k*8);
        }
        cudaEventRecord(g_hx.evJ, g_hx.sB);
        cudaStreamWaitEvent(0, g_hx.evJ, 0);
    } else {
        dim3 grid((MR+127)/128, Vz/128);
        k_logits16<<<grid, 256, LOG_SMEM>>>(
            (const __half*)pHf_h + Bz*Gz,
            (const __half*)pWoutf, b_out, out, MR, Vz, Gz, 0);
    }

    // ---- tuple tail ----
    if ((long)out_size > (long)Bz*Tz*Vz)
        k_tail<<<(Bz*Sz+255)/256, 256>>>(sent, slen, out, (long)out_size);
}

// round 16
// speedup vs baseline: 1.1977x; 1.1977x over previous
#include <cuda_runtime.h>
#include <cuda_bf16.h>
#include <cuda_fp16.h>
#include <cstdint>

typedef __nv_bfloat16 bf16;

#define Bz   32
#define Sz   128
#define Tz   127
#define Vz   32000
#define Ez   512
#define Gz   1024
#define HIz  512
#define G4z  4096
#define MR   4064   /* Tz*Bz */

// ------------------------- static device scratch -------------------------
__device__ __half g_Woutf[(size_t)Vz*Gz];           // fp16 hi of W_out
__device__ bf16  g_Wih_hi[(size_t)G4z*Ez];
__device__ bf16  g_Wih_lo[(size_t)G4z*Ez];
__device__ bf16  g_Whh_hi[(size_t)G4z*Gz];
__device__ bf16  g_Whh_lo[(size_t)G4z*Gz];
__device__ bf16  g_H_hi[(size_t)(Tz+2)*Bz*Gz];      // bf16 h for recurrence
__device__ bf16  g_H_lo[(size_t)(Tz+2)*Bz*Gz];
__device__ __half g_Hf_hi[(size_t)(Tz+2)*Bz*Gz];    // fp16 h for logits
__device__ bf16  g_X_hi[(size_t)MR*Ez];
__device__ bf16  g_X_lo[(size_t)MR*Ez];
__device__ float g_Xg[(size_t)MR*G4z];
__device__ float g_c[Bz*Gz];
__device__ float g_Q[Bz*HIz];
__device__ float g_Kb[Bz*16*HIz];
__device__ float g_Vb[Bz*16*HIz];
__device__ float g_ctx[Bz*HIz];
__device__ float g_att[Bz*HIz];
__device__ float g_ff[Bz*3*HIz];
__device__ float g_ie[Bz*Ez];
__device__ float g_g0[Bz*G4z];
__device__ float g_bsum[G4z];
// prologue split buffers (bf16 hi/lo)
__device__ bf16 g_ent_h[Bz*HIz],   g_ent_l[Bz*HIz];
__device__ bf16 g_nei_h[Bz*16*HIz],g_nei_l[Bz*16*HIz];
__device__ bf16 g_ctx_h[Bz*HIz],   g_ctx_l[Bz*HIz];
__device__ bf16 g_ffs_h[Bz*3*HIz], g_ffs_l[Bz*3*HIz];
__device__ bf16 g_ie_h[Bz*Ez],     g_ie_l[Bz*Ez];
__device__ bf16 g_Wq_h[HIz*HIz],   g_Wq_l[HIz*HIz];
__device__ bf16 g_Wk_h[HIz*HIz],   g_Wk_l[HIz*HIz];
__device__ bf16 g_Wv_h[HIz*HIz],   g_Wv_l[HIz*HIz];
__device__ bf16 g_Wo_h[HIz*HIz],   g_Wo_l[HIz*HIz];
__device__ bf16 g_Wim_h[Ez*3*HIz], g_Wim_l[Ez*3*HIz];

// ------------------------------ helpers ----------------------------------
__device__ __forceinline__ float sigf(float x){ return 1.0f/(1.0f+expf(-x)); }

__device__ __forceinline__ uint32_t smem_u32(const void* p){
    return (uint32_t)__cvta_generic_to_shared(p);
}
__device__ __forceinline__ void ldsmx4(uint32_t* r, const void* p){
    uint32_t a = smem_u32(p);
    asm volatile("ldmatrix.sync.aligned.m8n8.x4.shared.b16 {%0,%1,%2,%3},[%4];\n"
                 : "=r"(r[0]),"=r"(r[1]),"=r"(r[2]),"=r"(r[3]) : "r"(a));
}
__device__ __forceinline__ void ldsmx2(uint32_t* r, const void* p){
    uint32_t a = smem_u32(p);
    asm volatile("ldmatrix.sync.aligned.m8n8.x2.shared.b16 {%0,%1},[%2];\n"
                 : "=r"(r[0]),"=r"(r[1]) : "r"(a));
}
__device__ __forceinline__ void mma_bf(float* d, const uint32_t* a, const uint32_t* b){
    asm volatile("mma.sync.aligned.m16n8k16.row.col.f32.bf16.bf16.f32 "
                 "{%0,%1,%2,%3},{%4,%5,%6,%7},{%8,%9},{%0,%1,%2,%3};\n"
                 : "+f"(d[0]),"+f"(d[1]),"+f"(d[2]),"+f"(d[3])
                 : "r"(a[0]),"r"(a[1]),"r"(a[2]),"r"(a[3]),
                   "r"(b[0]),"r"(b[1]));
}
__device__ __forceinline__ void mma_fp(float* d, const uint32_t* a, const uint32_t* b){
    asm volatile("mma.sync.aligned.m16n8k16.row.col.f32.f16.f16.f32 "
                 "{%0,%1,%2,%3},{%4,%5,%6,%7},{%8,%9},{%0,%1,%2,%3};\n"
                 : "+f"(d[0]),"+f"(d[1]),"+f"(d[2]),"+f"(d[3])
                 : "r"(a[0]),"r"(a[1]),"r"(a[2]),"r"(a[3]),
                   "r"(b[0]),"r"(b[1]));
}
#define CP_ASYNC16P(dst, src, pv) \
    asm volatile("cp.async.cg.shared.global [%0], [%1], 16, %2;" \
                 :: "r"(dst), "l"(src), "r"(pv))
#define CP_ASYNC16(dst, src) \
    asm volatile("cp.async.cg.shared.global [%0], [%1], 16;" :: "r"(dst), "l"(src))
#define CP_COMMIT()  asm volatile("cp.async.commit_group;" ::: "memory")

// --------------------------- prep kernels --------------------------------
__global__ void k_split(const float* __restrict__ src, bf16* __restrict__ hi,
                        bf16* __restrict__ lo, int n){
    int i = blockIdx.x*blockDim.x + threadIdx.x;
    if (i < n){
        float x = src[i];
        bf16 h = __float2bfloat16(x);
        hi[i] = h;
        lo[i] = __float2bfloat16(x - __bfloat162float(h));
    }
}
__global__ void k_half(const float* __restrict__ src, __half* __restrict__ dst, int n){
    int i = blockIdx.x*blockDim.x + threadIdx.x;
    if (i < n) dst[i] = __float2half(src[i]);
}
__global__ void k_bsum(const float* __restrict__ a, const float* __restrict__ b){
    int i = blockIdx.x*blockDim.x + threadIdx.x;
    if (i < G4z) g_bsum[i] = a[i] + b[i];
}
__global__ void k_xgather(const float* __restrict__ emb, const int* __restrict__ sent){
    int i = blockIdx.x*blockDim.x + threadIdx.x;
    if (i < MR*Ez){
        int r = i >> 9, col = i & 511;
        int t = r >> 5, b = r & 31;
        int idx = sent[b*Sz + t];
        float v = emb[(size_t)idx*Ez + col];
        bf16 h = __float2bfloat16(v);
        g_X_hi[i] = h;
        g_X_lo[i] = __float2bfloat16(v - __bfloat162float(h));
    }
}
__global__ void k_ff(const float* __restrict__ ent, const float* __restrict__ img){
    int i = blockIdx.x*blockDim.x + threadIdx.x;
    if (i < Bz*HIz){
        int b = i >> 9, j = i & 511;
        float* row = g_ff + (size_t)b*3*HIz;
        row[j]          = ent[i];
        row[HIz + j]    = g_att[i];
        row[2*HIz + j]  = img[i];
    }
}

// ------------------------------ attention --------------------------------
__global__ void k_attn(const int* __restrict__ nnum){
    int bh = blockIdx.x;
    int b = bh >> 3, h = bh & 7;
    int d = threadIdx.x;                    // 64 threads
    __shared__ float red[64];
    __shared__ float sc[16];
    float q = g_Q[b*HIz + h*64 + d];
    for (int n = 0; n < 16; n++){
        red[d] = q * g_Kb[(size_t)(b*16+n)*HIz + h*64 + d];
        __syncthreads();
        for (int o = 32; o; o >>= 1){
            if (d < o) red[d] += red[d+o];
            __syncthreads();
        }
        if (d == 0) sc[n] = red[0]*0.125f;
        __syncthreads();
    }
    int num = nnum[b];
    float a[16], mx = -1e30f;
#pragma unroll
    for (int n = 0; n < 16; n++){
        a[n] = (n >= num) ? -1e9f : sc[n];
        mx = fmaxf(mx, a[n]);
    }
    float ssum = 0.f;
#pragma unroll
    for (int n = 0; n < 16; n++){ a[n] = expf(a[n]-mx); ssum += a[n]; }
    float inv = 1.f/ssum;
    float ctx = 0.f;
#pragma unroll
    for (int n = 0; n < 16; n++)
        ctx += a[n] * g_Vb[(size_t)(b*16+n)*HIz + h*64 + d];
    g_ctx[b*HIz + h*64 + d] = ctx*inv;
}

// --------------------------- first LSTM step -----------------------------
__global__ void k_step0(){
    int i = blockIdx.x*blockDim.x + threadIdx.x;
    if (i < Bz*Gz){
        int b = i >> 10, j = i & 1023;
        const float* g0 = g_g0 + (size_t)b*G4z;
        float gi = g0[j], gg = g0[j+2*Gz], go = g0[j+3*Gz];
        float c = sigf(gi)*tanhf(gg);
        float h = sigf(go)*tanhf(c);
        g_c[i] = c;
        bf16 hh = __float2bfloat16(h);
        g_H_hi[i] = hh;
        g_H_lo[i] = __float2bfloat16(h - __bfloat162float(hh));
    }
}

// ---- fused recurrence step: 128 blocks x 256 thr, K-split warp groups ---
// Block nb owns gate cols {nb*8..+7} across all 4 quadrants.
// warp q = warp&3 -> quadrant, half = warp>>2 -> K-half [0,512)/[512,1024).
// 3-stage cp.async over 8 chunks of K=128; partials reduced via sG.
#define SLD3 136
#define ST3_MAT (32*SLD3*2)      /* 8704 B per 32x128 bf16 matrix */
#define ST3_STG (4*ST3_MAT)      /* Ahi,Alo,Bhi,Blo = 34816 */
#define STEP_SMEM (3*ST3_STG)    /* 104448 */
__global__ void __launch_bounds__(256, 1) k_step(int s){
    extern __shared__ char dsm[];
    __shared__ float sG[2][4][32][8];
    const uint32_t sb = smem_u32(dsm);
    const int tid = threadIdx.x, warp = tid >> 5, lane = tid & 31;
    const int q = warp & 3, half = warp >> 2;
    const int nb = blockIdx.x, c0 = nb*8;
    const bf16* hHi = g_H_hi + (size_t)s*Bz*Gz;
    const bf16* hLo = g_H_lo + (size_t)s*Bz*Gz;

    float acc[2][4];
#pragma unroll
    for (int a=0;a<2;a++)
#pragma unroll
    for (int c=0;c<4;c++) acc[a][c]=0.f;

    // per stage: 4 matrices x 32 rows x 16 chunks(16B) = 2048 cp.async / 256 thr
    auto load_stage = [&](int ch, int buf){
        const int kk = ch*128;
        const uint32_t s0 = sb + buf*ST3_STG;
#pragma unroll
        for (int i = 0; i < 2; i++){
            int u = tid + i*256;              // 0..511
            int r = u >> 4, cc = (u & 15)*8;  // row 0..31, elem col 0..120
            uint32_t so = (uint32_t)((r*SLD3 + cc)*2);
            int g = (r >> 3)*Gz + c0 + (r & 7);
            CP_ASYNC16(s0 + so,              hHi + (size_t)r*Gz + kk + cc);
            CP_ASYNC16(s0 + ST3_MAT + so,    hLo + (size_t)r*Gz + kk + cc);
            CP_ASYNC16(s0 + 2*ST3_MAT + so,  g_Whh_hi + (size_t)g*Gz + kk + cc);
            CP_ASYNC16(s0 + 3*ST3_MAT + so,  g_Whh_lo + (size_t)g*Gz + kk + cc);
        }
    };
    load_stage(0, 0); CP_COMMIT();
    load_stage(1, 1); CP_COMMIT();

    for (int ch = 0; ch < 8; ch++){
        asm volatile("cp.async.wait_group 1;" ::: "memory");
        __syncthreads();
        if (ch + 2 < 8) load_stage(ch + 2, (ch + 2) % 3);
        CP_COMMIT();
        const char* st = dsm + (ch % 3)*ST3_STG;
        const bf16* pA0 = (const bf16*)(st);
        const bf16* pA1 = (const bf16*)(st + ST3_MAT);
        const bf16* pB0 = (const bf16*)(st + 2*ST3_MAT);
        const bf16* pB1 = (const bf16*)(st + 3*ST3_MAT);
#pragma unroll
        for (int ksl = 0; ksl < 4; ksl++){
            const int ks = half*64 + ksl*16;
            uint32_t ah[2][4], al[2][4], bh[2], bl[2];
#pragma unroll
            for (int mi = 0; mi < 2; mi++){
                int row = mi*16 + (lane & 15);
                int kc  = ks + (lane >> 4)*8;
                ldsmx4(ah[mi], pA0 + row*SLD3 + kc);
                ldsmx4(al[mi], pA1 + row*SLD3 + kc);
            }
            {
                int l = lane & 15;
                int row = q*8 + (l & 7);
                int kc  = ks + ((l >> 3) & 1)*8;
                ldsmx2(bh, pB0 + row*SLD3 + kc);
                ldsmx2(bl, pB1 + row*SLD3 + kc);
            }
#pragma unroll
            for (int mi = 0; mi < 2; mi++){
                mma_bf(acc[mi], ah[mi], bh);
                mma_bf(acc[mi], ah[mi], bl);
                mma_bf(acc[mi], al[mi], bh);
            }
        }
    }
    // scatter partials: [half][quadrant]
#pragma unroll
    for (int mi = 0; mi < 2; mi++)
#pragma unroll
    for (int h = 0; h < 2; h++){
        int b  = mi*16 + (lane >> 2) + h*8;
        int jl = (lane & 3)*2;
        sG[half][q][b][jl]   = acc[mi][h*2];
        sG[half][q][b][jl+1] = acc[mi][h*2+1];
    }
    __syncthreads();
    // LSTM cell update: one element per thread (32x8 = 256)
    bf16* oHi = g_H_hi + (size_t)(s+1)*Bz*Gz;
    bf16* oLo = g_H_lo + (size_t)(s+1)*Bz*Gz;
    __half* fHi = g_Hf_hi + (size_t)(s+1)*Bz*Gz;
    const float* Xg = g_Xg + (size_t)s*Bz*G4z;
    {
        int b = tid >> 3, jl = tid & 7;
        int col = c0 + jl;
        const float* xg = Xg + (size_t)b*G4z;
        float gi = sG[0][0][b][jl] + sG[1][0][b][jl] + xg[col];
        float gf = sG[0][1][b][jl] + sG[1][1][b][jl] + xg[col +   Gz];
        float gg = sG[0][2][b][jl] + sG[1][2][b][jl] + xg[col + 2*Gz];
        float go = sG[0][3][b][jl] + sG[1][3][b][jl] + xg[col + 3*Gz];
        float c = sigf(gf)*g_c[b*Gz+col] + sigf(gi)*tanhf(gg);
        float h = sigf(go)*tanhf(c);
        g_c[b*Gz+col] = c;
        bf16 hb = __float2bfloat16(h);
        oHi[b*Gz+col] = hb;
        oLo[b*Gz+col] = __float2bfloat16(h - __bfloat162float(hb));
        fHi[b*Gz+col] = __float2half(h);
    }
}

// ------ pipelined split-bf16 3-term GEMM (Xg + prologue), act 0/1=tanh ---
#define LDT   40
#define MATB  (128*LDT*2)
#define STGB  (4*MATB)
#define GEMM_SMEM (3*STGB)       /* 122880 */
__global__ void __launch_bounds__(256, 1) k_gemm3p(
    const bf16* __restrict__ Ahi, const bf16* __restrict__ Alo,
    const bf16* __restrict__ Bhi, const bf16* __restrict__ Blo,
    const float* __restrict__ bias, float* __restrict__ out,
    int M, int N, int K, int act)
{
    extern __shared__ char smem[];
    const uint32_t sb = smem_u32(smem);
    const int tid = threadIdx.x, warp = tid >> 5, lane = tid & 31;
    const int m0 = blockIdx.x*128, n0 = blockIdx.y*128;
    const int wm = (warp >> 2)*64, wn = (warp & 3)*32;
    const int NC = K >> 5;

    float acc[4][4][4];
#pragma unroll
    for (int a=0;a<4;a++)
#pragma unroll
    for (int b=0;b<4;b++)
#pragma unroll
    for (int c=0;c<4;c++) acc[a][b][c]=0.f;

    auto load_stage = [&](int chunk, int buf){
        const int kk = chunk << 5;
        const uint32_t s0 = sb + buf*STGB;
#pragma unroll
        for (int i = 0; i < 2; i++){
            int u = tid + i*256;
            int r = u >> 2, c = (u & 3)*8;
            uint32_t so = (uint32_t)((r*LDT + c)*2);
            int gr = m0 + r;
            uint32_t pv = (gr < M) ? 16u : 0u;
            int grc = gr < M ? gr : (M-1);
            CP_ASYNC16P(s0 + so,          Ahi + (size_t)grc*K + kk + c, pv);
            CP_ASYNC16P(s0 + MATB + so,   Alo + (size_t)grc*K + kk + c, pv);
            int gn = n0 + r;
            CP_ASYNC16(s0 + 2*MATB + so,  Bhi + (size_t)gn*K + kk + c);
            CP_ASYNC16(s0 + 3*MATB + so,  Blo + (size_t)gn*K + kk + c);
        }
    };
    load_stage(0, 0); CP_COMMIT();
    if (NC > 1){ load_stage(1, 1); } CP_COMMIT();

    for (int c = 0; c < NC; c++){
        asm volatile("cp.async.wait_group 1;" ::: "memory");
        __syncthreads();
        if (c + 2 < NC) load_stage(c + 2, (c + 2) % 3);
        CP_COMMIT();
        const char* st = smem + (c % 3)*STGB;
        const bf16* pA0 = (const bf16*)(st);
        const bf16* pA1 = (const bf16*)(st + MATB);
        const bf16* pB0 = (const bf16*)(st + 2*MATB);
        const bf16* pB1 = (const bf16*)(st + 3*MATB);
#pragma unroll
        for (int ks = 0; ks < 32; ks += 16){
            uint32_t ah[4][4], al[4][4], bh[2][4], bl[2][4];
#pragma unroll
            for (int mi = 0; mi < 4; mi++){
                int row = wm + mi*16 + (lane & 15);
                int kc  = ks + (lane >> 4)*8;
                ldsmx4(ah[mi], pA0 + row*LDT + kc);
                ldsmx4(al[mi], pA1 + row*LDT + kc);
            }
#pragma unroll
            for (int ni = 0; ni < 2; ni++){
                int j = lane >> 3;
                int row = wn + ni*16 + ((j >> 1)*8) + (lane & 7);
                int kc  = ks + (j & 1)*8;
                ldsmx4(bh[ni], pB0 + row*LDT + kc);
                ldsmx4(bl[ni], pB1 + row*LDT + kc);
            }
#pragma unroll
            for (int mi = 0; mi < 4; mi++)
#pragma unroll
                for (int nj = 0; nj < 4; nj++){
                    const uint32_t* fh = &bh[nj >> 1][(nj & 1)*2];
                    const uint32_t* fl = &bl[nj >> 1][(nj & 1)*2];
                    mma_bf(acc[mi][nj], ah[mi], fh);
                    mma_bf(acc[mi][nj], ah[mi], fl);
                    mma_bf(acc[mi][nj], al[mi], fh);
                }
        }
    }
#pragma unroll
    for (int mi = 0; mi < 4; mi++)
#pragma unroll
    for (int nj = 0; nj < 4; nj++){
        int n = n0 + wn + nj*8 + (lane & 3)*2;
        float b0 = bias[n], b1 = bias[n+1];
#pragma unroll
        for (int h = 0; h < 2; h++){
            int m = m0 + wm + mi*16 + (lane >> 2) + h*8;
            if (m < M){
                float v0 = acc[mi][nj][h*2]   + b0;
                float v1 = acc[mi][nj][h*2+1] + b1;
                if (act == 1){ v0 = tanhf(v0); v1 = tanhf(v1); }
                out[(size_t)m*N + n]   = v0;
                out[(size_t)m*N + n+1] = v1;
            }
        }
    }
}

// ---- logits: fp16 1-term pipelined GEMM, BK=64, D = Ah @ Bh^T + bias ----
// remap: row m = t*32+b  ->  out[(b*127+t)*Vz + n]
#define LDTL  72
#define MATL  (128*LDTL*2)       /* 18432 */
#define STGL  (2*MATL)           /* Ah, Bh = 36864 */
#define LOG_SMEM (3*STGL)        /* 110592 */
__global__ void __launch_bounds__(256, 1) k_logits16(
    const __half* __restrict__ Ahi,
    const __half* __restrict__ Bhi,
    const float* __restrict__ bias, float* __restrict__ out,
    int M, int N, int K)
{
    extern __shared__ char smem[];
    const uint32_t sb = smem_u32(smem);
    const int tid = threadIdx.x, warp = tid >> 5, lane = tid & 31;
    const int m0 = blockIdx.x*128, n0 = blockIdx.y*128;
    const int wm = (warp >> 2)*64, wn = (warp & 3)*32;
    const int NC = K >> 6;       // chunks of 64

    float acc[4][4][4];
#pragma unroll
    for (int a=0;a<4;a++)
#pragma unroll
    for (int b=0;b<4;b++)
#pragma unroll
    for (int c=0;c<4;c++) acc[a][b][c]=0.f;

    auto load_stage = [&](int chunk, int buf){
        const int kk = chunk << 6;
        const uint32_t s0 = sb + buf*STGL;
#pragma unroll
        for (int i = 0; i < 4; i++){
            int u = tid + i*256;                 // 0..1023
            int r = u >> 3, c = (u & 7)*8;
            uint32_t so = (uint32_t)((r*LDTL + c)*2);
            int gr = m0 + r;
            uint32_t pv = (gr < M) ? 16u : 0u;
            int grc = gr < M ? gr : (M-1);
            CP_ASYNC16P(s0 + so,        Ahi + (size_t)grc*K + kk + c, pv);
            int gn = n0 + r;
            CP_ASYNC16(s0 + MATL + so,  Bhi + (size_t)gn*K + kk + c);
        }
    };
    load_stage(0, 0); CP_COMMIT();
    load_stage(1, 1); CP_COMMIT();

    for (int c = 0; c < NC; c++){
        asm volatile("cp.async.wait_group 1;" ::: "memory");
        __syncthreads();
        if (c + 2 < NC) load_stage(c + 2, (c + 2) % 3);
        CP_COMMIT();
        const char* st = smem + (c % 3)*STGL;
        const __half* pA0 = (const __half*)(st);
        const __half* pB0 = (const __half*)(st + MATL);
#pragma unroll
        for (int ks = 0; ks < 64; ks += 16){
            uint32_t ah[4][4], bh[2][4];
#pragma unroll
            for (int mi = 0; mi < 4; mi++){
                int row = wm + mi*16 + (lane & 15);
                int kc  = ks + (lane >> 4)*8;
                ldsmx4(ah[mi], pA0 + row*LDTL + kc);
            }
#pragma unroll
            for (int ni = 0; ni < 2; ni++){
                int j = lane >> 3;
                int row = wn + ni*16 + ((j >> 1)*8) + (lane & 7);
                int kc  = ks + (j & 1)*8;
                ldsmx4(bh[ni], pB0 + row*LDTL + kc);
            }
#pragma unroll
            for (int mi = 0; mi < 4; mi++)
#pragma unroll
                for (int nj = 0; nj < 4; nj++){
                    const uint32_t* fh = &bh[nj >> 1][(nj & 1)*2];
                    mma_fp(acc[mi][nj], ah[mi], fh);
                }
        }
    }
#pragma unroll
    for (int mi = 0; mi < 4; mi++)
#pragma unroll
    for (int nj = 0; nj < 4; nj++){
        int n = n0 + wn + nj*8 + (lane & 3)*2;
        float b0 = bias[n], b1 = bias[n+1];
#pragma unroll
        for (int h = 0; h < 2; h++){
            int m = m0 + wm + mi*16 + (lane >> 2) + h*8;
            if (m < M){
                int t = m >> 5, b = m & 31;
                size_t off = ((size_t)b*Tz + t)*(size_t)N + n;
                out[off]   = acc[mi][nj][h*2]   + b0;
                out[off+1] = acc[mi][nj][h*2+1] + b1;
            }
        }
    }
}

// ------------------------------- tail ------------------------------------
__global__ void k_tail(const int* __restrict__ sent, const int* __restrict__ slen,
                       float* __restrict__ out, long out_size){
    long base = (long)Bz*Tz*Vz;
    int i = blockIdx.x*blockDim.x + threadIdx.x;
    if (i < Bz*Sz && base + i < out_size)            out[base+i] = (float)sent[i];
    if (i < Bz && base + Bz*Sz + i < out_size)       out[base+Bz*Sz+i] = (float)slen[i];
}

// ------------------------------ host side --------------------------------
static inline void* sym(const void* s){ void* p; cudaGetSymbolAddress(&p, s); return p; }

extern "C" void kernel_launch(void* const* d_in, const int* in_sizes, int n_in,
                              void* d_out, int out_size) {
    const float* ent   = (const float*)d_in[0];
    const float* neigh = (const float*)d_in[1];
    const int*   nnum  = (const int*)  d_in[2];
    const float* img   = (const float*)d_in[3];
    const int*   sent  = (const int*)  d_in[4];
    const int*   slen  = (const int*)  d_in[5];
    const float* emb   = (const float*)d_in[6];
    const float* W_ih  = (const float*)d_in[7];
    const float* W_hh  = (const float*)d_in[8];
    const float* b_ih  = (const float*)d_in[9];
    const float* b_hh  = (const float*)d_in[10];
    const float* W_img = (const float*)d_in[11];
    const float* b_img = (const float*)d_in[12];
    const float* W_out = (const float*)d_in[13];
    const float* b_out = (const float*)d_in[14];
    const float* Wq = (const float*)d_in[15]; const float* bq = (const float*)d_in[16];
    const float* Wk = (const float*)d_in[17]; const float* bk = (const float*)d_in[18];
    const float* Wv = (const float*)d_in[19]; const float* bv = (const float*)d_in[20];
    const float* Wo = (const float*)d_in[21]; const float* bo = (const float*)d_in[22];
    float* out = (float*)d_out;

    void *pWoutf = sym(g_Woutf);
    void *pWih_h = sym(g_Wih_hi), *pWih_l = sym(g_Wih_lo);
    void *pWhh_h = sym(g_Whh_hi), *pWhh_l = sym(g_Whh_lo);
    void *pHf_h = sym(g_Hf_hi);
    void *pXh = sym(g_X_hi), *pXl = sym(g_X_lo);
    void *pXg = sym(g_Xg), *pBsum = sym(g_bsum);
    void *pQ = sym(g_Q), *pKb = sym(g_Kb), *pVb = sym(g_Vb);
    void *pCtx = sym(g_ctx), *pAtt = sym(g_att), *pFf = sym(g_ff);
    void *pIe = sym(g_ie), *pG0 = sym(g_g0);
    void *pEnt_h = sym(g_ent_h), *pEnt_l = sym(g_ent_l);
    void *pNei_h = sym(g_nei_h), *pNei_l = sym(g_nei_l);
    void *pCtx_h = sym(g_ctx_h), *pCtx_l = sym(g_ctx_l);
    void *pFfs_h = sym(g_ffs_h), *pFfs_l = sym(g_ffs_l);
    void *pIe_h = sym(g_ie_h), *pIe_l = sym(g_ie_l);
    void *pWq_h = sym(g_Wq_h), *pWq_l = sym(g_Wq_l);
    void *pWk_h = sym(g_Wk_h), *pWk_l = sym(g_Wk_l);
    void *pWv_h = sym(g_Wv_h), *pWv_l = sym(g_Wv_l);
    void *pWo_h = sym(g_Wo_h), *pWo_l = sym(g_Wo_l);
    void *pWim_h = sym(g_Wim_h), *pWim_l = sym(g_Wim_l);

    cudaFuncSetAttribute(k_gemm3p,  cudaFuncAttributeMaxDynamicSharedMemorySize, GEMM_SMEM);
    cudaFuncSetAttribute(k_logits16,cudaFuncAttributeMaxDynamicSharedMemorySize, LOG_SMEM);
    cudaFuncSetAttribute(k_step,    cudaFuncAttributeMaxDynamicSharedMemorySize, STEP_SMEM);

    // ---- prep part 1 (ordered so launch #4 = Xg GEMM for ncu capture) ----
    {
        int n = G4z*Ez;
        k_split<<<(n+255)/256, 256>>>(W_ih, (bf16*)pWih_h, (bf16*)pWih_l, n);   // 1
        n = MR*Ez;
        k_xgather<<<(n+255)/256, 256>>>(emb, sent);                             // 2
        k_bsum<<<(G4z+255)/256, 256>>>(b_ih, b_hh);                             // 3
        dim3 grid((MR+127)/128, G4z/128);                                       // 4: Xg
        k_gemm3p<<<grid, 256, GEMM_SMEM>>>((bf16*)pXh, (bf16*)pXl,
                               (bf16*)pWih_h, (bf16*)pWih_l,
                               (const float*)pBsum, (float*)pXg,
                               MR, G4z, Ez, 0);
    }
    // ---- prep part 2 ----
    {
        int n = Vz*Gz;
        k_half<<<(n+255)/256, 256>>>(W_out, (__half*)pWoutf, n);
        n = G4z*Gz;
        k_split<<<(n+255)/256, 256>>>(W_hh, (bf16*)pWhh_h, (bf16*)pWhh_l, n);
        n = HIz*HIz;
        k_split<<<(n+255)/256, 256>>>(Wq, (bf16*)pWq_h, (bf16*)pWq_l, n);
        k_split<<<(n+255)/256, 256>>>(Wk, (bf16*)pWk_h, (bf16*)pWk_l, n);
        k_split<<<(n+255)/256, 256>>>(Wv, (bf16*)pWv_h, (bf16*)pWv_l, n);
        k_split<<<(n+255)/256, 256>>>(Wo, (bf16*)pWo_h, (bf16*)pWo_l, n);
        n = Ez*3*HIz;
        k_split<<<(n+255)/256, 256>>>(W_img, (bf16*)pWim_h, (bf16*)pWim_l, n);
        n = Bz*HIz;
        k_split<<<(n+255)/256, 256>>>(ent, (bf16*)pEnt_h, (bf16*)pEnt_l, n);
        n = Bz*16*HIz;
        k_split<<<(n+255)/256, 256>>>(neigh, (bf16*)pNei_h, (bf16*)pNei_l, n);
    }

    // ---- prologue: MHA + img_embed + first LSTM step (tensor-core GEMMs) ----
    {
        dim3 g1(1, HIz/128), g4(4, HIz/128);
        k_gemm3p<<<g1, 256, GEMM_SMEM>>>((bf16*)pEnt_h, (bf16*)pEnt_l,
            (bf16*)pWq_h, (bf16*)pWq_l, bq, (float*)pQ, Bz, HIz, HIz, 0);
        k_gemm3p<<<g4, 256, GEMM_SMEM>>>((bf16*)pNei_h, (bf16*)pNei_l,
            (bf16*)pWk_h, (bf16*)pWk_l, bk, (float*)pKb, Bz*16, HIz, HIz, 0);
        k_gemm3p<<<g4, 256, GEMM_SMEM>>>((bf16*)pNei_h, (bf16*)pNei_l,
            (bf16*)pWv_h, (bf16*)pWv_l, bv, (float*)pVb, Bz*16, HIz, HIz, 0);
        k_attn<<<Bz*8, 64>>>(nnum);
        int n = Bz*HIz;
        k_split<<<(n+255)/256, 256>>>((const float*)pCtx, (bf16*)pCtx_h, (bf16*)pCtx_l, n);
        k_gemm3p<<<g1, 256, GEMM_SMEM>>>((bf16*)pCtx_h, (bf16*)pCtx_l,
            (bf16*)pWo_h, (bf16*)pWo_l, bo, (float*)pAtt, Bz, HIz, HIz, 0);
        k_ff<<<(Bz*HIz+255)/256, 256>>>(ent, img);
        n = Bz*3*HIz;
        k_split<<<(n+255)/256, 256>>>((const float*)pFf, (bf16*)pFfs_h, (bf16*)pFfs_l, n);
        k_gemm3p<<<g1, 256, GEMM_SMEM>>>((bf16*)pFfs_h, (bf16*)pFfs_l,
            (bf16*)pWim_h, (bf16*)pWim_l, b_img, (float*)pIe, Bz, HIz, 3*HIz, 1);
        n = Bz*Ez;
        k_split<<<(n+255)/256, 256>>>((const float*)pIe, (bf16*)pIe_h, (bf16*)pIe_l, n);
        dim3 gg(1, G4z/128);
        k_gemm3p<<<gg, 256, GEMM_SMEM>>>((bf16*)pIe_h, (bf16*)pIe_l,
            (bf16*)pWih_h, (bf16*)pWih_l, (const float*)pBsum, (float*)pG0, Bz, G4z, Ez, 0);
        k_step0<<<(Bz*Gz+255)/256, 256>>>();
    }

    // ---- recurrence: 127 fused steps, 128 blocks x 256 thr ----
    for (int s = 0; s < Tz; s++)
        k_step<<<128, 256, STEP_SMEM>>>(s);

    // ---- logits: fp16 1-term BK=64 [4064,1024]x[1024,32000], remap [B,T,V] ----
    {
        dim3 grid((MR+127)/128, Vz/128);   // 32 x 250
        k_logits16<<<grid, 256, LOG_SMEM>>>(
            (const __half*)pHf_h + Bz*Gz,
            (const __half*)pWoutf, b_out, out, MR, Vz, Gz);
    }

    // ---- tuple tail ----
    if ((long)out_size > (long)Bz*Tz*Vz)
        k_tail<<<(Bz*Sz+255)/256, 256>>>(sent, slen, out, (long)out_size);
}

// round 17
// speedup vs baseline: 1.2968x; 1.0827x over previous
#include <cuda_runtime.h>
#include <cuda_bf16.h>
#include <cuda_fp16.h>
#include <cstdint>

typedef __nv_bfloat16 bf16;

#define Bz   32
#define Sz   128
#define Tz   127
#define Vz   32000
#define Ez   512
#define Gz   1024
#define HIz  512
#define G4z  4096
#define MR   4064   /* Tz*Bz */

// ------------------------- static device scratch -------------------------
__device__ __half g_Woutf[(size_t)Vz*Gz];           // fp16 hi of W_out
__device__ bf16  g_Wih_hi[(size_t)G4z*Ez];
__device__ bf16  g_Wih_lo[(size_t)G4z*Ez];
__device__ bf16  g_Whh_hi[(size_t)G4z*Gz];
__device__ bf16  g_Whh_lo[(size_t)G4z*Gz];
__device__ bf16  g_H_hi[(size_t)(Tz+2)*Bz*Gz];      // bf16 h for recurrence
__device__ bf16  g_H_lo[(size_t)(Tz+2)*Bz*Gz];
__device__ __half g_Hf_hi[(size_t)(Tz+2)*Bz*Gz];    // fp16 h for logits
__device__ bf16  g_X_hi[(size_t)MR*Ez];
__device__ bf16  g_X_lo[(size_t)MR*Ez];
__device__ float g_Xg[(size_t)MR*G4z];
__device__ float g_c[Bz*Gz];
__device__ float g_Q[Bz*HIz];
__device__ float g_Kb[Bz*16*HIz];
__device__ float g_Vb[Bz*16*HIz];
__device__ float g_ctx[Bz*HIz];
__device__ float g_att[Bz*HIz];
__device__ float g_ff[Bz*3*HIz];
__device__ float g_ie[Bz*Ez];
__device__ float g_g0[Bz*G4z];
__device__ float g_bsum[G4z];
// prologue split buffers (bf16 hi/lo)
__device__ bf16 g_ent_h[Bz*HIz],   g_ent_l[Bz*HIz];
__device__ bf16 g_nei_h[Bz*16*HIz],g_nei_l[Bz*16*HIz];
__device__ bf16 g_ctx_h[Bz*HIz],   g_ctx_l[Bz*HIz];
__device__ bf16 g_ffs_h[Bz*3*HIz], g_ffs_l[Bz*3*HIz];
__device__ bf16 g_ie_h[Bz*Ez],     g_ie_l[Bz*Ez];
__device__ bf16 g_Wq_h[HIz*HIz],   g_Wq_l[HIz*HIz];
__device__ bf16 g_Wk_h[HIz*HIz],   g_Wk_l[HIz*HIz];
__device__ bf16 g_Wv_h[HIz*HIz],   g_Wv_l[HIz*HIz];
__device__ bf16 g_Wo_h[HIz*HIz],   g_Wo_l[HIz*HIz];
__device__ bf16 g_Wim_h[Ez*3*HIz], g_Wim_l[Ez*3*HIz];

// ------------------------------ helpers ----------------------------------
__device__ __forceinline__ float sigf(float x){ return 1.0f/(1.0f+expf(-x)); }

__device__ __forceinline__ uint32_t smem_u32(const void* p){
    return (uint32_t)__cvta_generic_to_shared(p);
}
__device__ __forceinline__ void ldsmx4(uint32_t* r, const void* p){
    uint32_t a = smem_u32(p);
    asm volatile("ldmatrix.sync.aligned.m8n8.x4.shared.b16 {%0,%1,%2,%3},[%4];\n"
                 : "=r"(r[0]),"=r"(r[1]),"=r"(r[2]),"=r"(r[3]) : "r"(a));
}
__device__ __forceinline__ void ldsmx2(uint32_t* r, const void* p){
    uint32_t a = smem_u32(p);
    asm volatile("ldmatrix.sync.aligned.m8n8.x2.shared.b16 {%0,%1},[%2];\n"
                 : "=r"(r[0]),"=r"(r[1]) : "r"(a));
}
__device__ __forceinline__ void mma_bf(float* d, const uint32_t* a, const uint32_t* b){
    asm volatile("mma.sync.aligned.m16n8k16.row.col.f32.bf16.bf16.f32 "
                 "{%0,%1,%2,%3},{%4,%5,%6,%7},{%8,%9},{%0,%1,%2,%3};\n"
                 : "+f"(d[0]),"+f"(d[1]),"+f"(d[2]),"+f"(d[3])
                 : "r"(a[0]),"r"(a[1]),"r"(a[2]),"r"(a[3]),
                   "r"(b[0]),"r"(b[1]));
}
__device__ __forceinline__ void mma_fp(float* d, const uint32_t* a, const uint32_t* b){
    asm volatile("mma.sync.aligned.m16n8k16.row.col.f32.f16.f16.f32 "
                 "{%0,%1,%2,%3},{%4,%5,%6,%7},{%8,%9},{%0,%1,%2,%3};\n"
                 : "+f"(d[0]),"+f"(d[1]),"+f"(d[2]),"+f"(d[3])
                 : "r"(a[0]),"r"(a[1]),"r"(a[2]),"r"(a[3]),
                   "r"(b[0]),"r"(b[1]));
}
#define CP_ASYNC16P(dst, src, pv) \
    asm volatile("cp.async.cg.shared.global [%0], [%1], 16, %2;" \
                 :: "r"(dst), "l"(src), "r"(pv))
#define CP_ASYNC16(dst, src) \
    asm volatile("cp.async.cg.shared.global [%0], [%1], 16;" :: "r"(dst), "l"(src))
#define CP_COMMIT()  asm volatile("cp.async.commit_group;" ::: "memory")

// --------------------------- prep kernels --------------------------------
__global__ void k_split(const float* __restrict__ src, bf16* __restrict__ hi,
                        bf16* __restrict__ lo, int n){
    int i = blockIdx.x*blockDim.x + threadIdx.x;
    if (i < n){
        float x = src[i];
        bf16 h = __float2bfloat16(x);
        hi[i] = h;
        lo[i] = __float2bfloat16(x - __bfloat162float(h));
    }
}
__global__ void k_half(const float* __restrict__ src, __half* __restrict__ dst, int n){
    int i = blockIdx.x*blockDim.x + threadIdx.x;
    if (i < n) dst[i] = __float2half(src[i]);
}
__global__ void k_bsum(const float* __restrict__ a, const float* __restrict__ b){
    int i = blockIdx.x*blockDim.x + threadIdx.x;
    if (i < G4z) g_bsum[i] = a[i] + b[i];
}
__global__ void k_xgather(const float* __restrict__ emb, const int* __restrict__ sent){
    int i = blockIdx.x*blockDim.x + threadIdx.x;
    if (i < MR*Ez){
        int r = i >> 9, col = i & 511;
        int t = r >> 5, b = r & 31;
        int idx = sent[b*Sz + t];
        float v = emb[(size_t)idx*Ez + col];
        bf16 h = __float2bfloat16(v);
        g_X_hi[i] = h;
        g_X_lo[i] = __float2bfloat16(v - __bfloat162float(h));
    }
}
__global__ void k_ff(const float* __restrict__ ent, const float* __restrict__ img){
    int i = blockIdx.x*blockDim.x + threadIdx.x;
    if (i < Bz*HIz){
        int b = i >> 9, j = i & 511;
        float* row = g_ff + (size_t)b*3*HIz;
        row[j]          = ent[i];
        row[HIz + j]    = g_att[i];
        row[2*HIz + j]  = img[i];
    }
}

// ------------------------------ attention --------------------------------
__global__ void k_attn(const int* __restrict__ nnum){
    int bh = blockIdx.x;
    int b = bh >> 3, h = bh & 7;
    int d = threadIdx.x;                    // 64 threads
    __shared__ float red[64];
    __shared__ float sc[16];
    float q = g_Q[b*HIz + h*64 + d];
    for (int n = 0; n < 16; n++){
        red[d] = q * g_Kb[(size_t)(b*16+n)*HIz + h*64 + d];
        __syncthreads();
        for (int o = 32; o; o >>= 1){
            if (d < o) red[d] += red[d+o];
            __syncthreads();
        }
        if (d == 0) sc[n] = red[0]*0.125f;
        __syncthreads();
    }
    int num = nnum[b];
    float a[16], mx = -1e30f;
#pragma unroll
    for (int n = 0; n < 16; n++){
        a[n] = (n >= num) ? -1e9f : sc[n];
        mx = fmaxf(mx, a[n]);
    }
    float ssum = 0.f;
#pragma unroll
    for (int n = 0; n < 16; n++){ a[n] = expf(a[n]-mx); ssum += a[n]; }
    float inv = 1.f/ssum;
    float ctx = 0.f;
#pragma unroll
    for (int n = 0; n < 16; n++)
        ctx += a[n] * g_Vb[(size_t)(b*16+n)*HIz + h*64 + d];
    g_ctx[b*HIz + h*64 + d] = ctx*inv;
}

// --------------------------- first LSTM step -----------------------------
__global__ void k_step0(){
    int i = blockIdx.x*blockDim.x + threadIdx.x;
    if (i < Bz*Gz){
        int b = i >> 10, j = i & 1023;
        const float* g0 = g_g0 + (size_t)b*G4z;
        float gi = g0[j], gg = g0[j+2*Gz], go = g0[j+3*Gz];
        float c = sigf(gi)*tanhf(gg);
        float h = sigf(go)*tanhf(c);
        g_c[i] = c;
        bf16 hh = __float2bfloat16(h);
        g_H_hi[i] = hh;
        g_H_lo[i] = __float2bfloat16(h - __bfloat162float(hh));
    }
}

// ---- fused recurrence step: 128 blocks x 256 thr, K-split warp groups ---
// Block nb owns gate cols {nb*8..+7} across all 4 quadrants.
// warp q = warp&3 -> quadrant, half = warp>>2 -> K-half [0,512)/[512,1024).
// 3-stage cp.async over 8 chunks of K=128; partials reduced via sG.
#define SLD3 136
#define ST3_MAT (32*SLD3*2)      /* 8704 B per 32x128 bf16 matrix */
#define ST3_STG (4*ST3_MAT)      /* Ahi,Alo,Bhi,Blo = 34816 */
#define STEP_SMEM (3*ST3_STG)    /* 104448 */
__global__ void __launch_bounds__(256, 1) k_step(int s){
    extern __shared__ char dsm[];
    __shared__ float sG[2][4][32][8];
    const uint32_t sb = smem_u32(dsm);
    const int tid = threadIdx.x, warp = tid >> 5, lane = tid & 31;
    const int q = warp & 3, half = warp >> 2;
    const int nb = blockIdx.x, c0 = nb*8;
    const bf16* hHi = g_H_hi + (size_t)s*Bz*Gz;
    const bf16* hLo = g_H_lo + (size_t)s*Bz*Gz;

    float acc[2][4];
#pragma unroll
    for (int a=0;a<2;a++)
#pragma unroll
    for (int c=0;c<4;c++) acc[a][c]=0.f;

    // per stage: 4 matrices x 32 rows x 16 chunks(16B) = 2048 cp.async / 256 thr
    auto load_stage = [&](int ch, int buf){
        const int kk = ch*128;
        const uint32_t s0 = sb + buf*ST3_STG;
#pragma unroll
        for (int i = 0; i < 2; i++){
            int u = tid + i*256;              // 0..511
            int r = u >> 4, cc = (u & 15)*8;  // row 0..31, elem col 0..120
            uint32_t so = (uint32_t)((r*SLD3 + cc)*2);
            int g = (r >> 3)*Gz + c0 + (r & 7);
            CP_ASYNC16(s0 + so,              hHi + (size_t)r*Gz + kk + cc);
            CP_ASYNC16(s0 + ST3_MAT + so,    hLo + (size_t)r*Gz + kk + cc);
            CP_ASYNC16(s0 + 2*ST3_MAT + so,  g_Whh_hi + (size_t)g*Gz + kk + cc);
            CP_ASYNC16(s0 + 3*ST3_MAT + so,  g_Whh_lo + (size_t)g*Gz + kk + cc);
        }
    };
    load_stage(0, 0); CP_COMMIT();
    load_stage(1, 1); CP_COMMIT();

    for (int ch = 0; ch < 8; ch++){
        asm volatile("cp.async.wait_group 1;" ::: "memory");
        __syncthreads();
        if (ch + 2 < 8) load_stage(ch + 2, (ch + 2) % 3);
        CP_COMMIT();
        const char* st = dsm + (ch % 3)*ST3_STG;
        const bf16* pA0 = (const bf16*)(st);
        const bf16* pA1 = (const bf16*)(st + ST3_MAT);
        const bf16* pB0 = (const bf16*)(st + 2*ST3_MAT);
        const bf16* pB1 = (const bf16*)(st + 3*ST3_MAT);
#pragma unroll
        for (int ksl = 0; ksl < 4; ksl++){
            const int ks = half*64 + ksl*16;
            uint32_t ah[2][4], al[2][4], bh[2], bl[2];
#pragma unroll
            for (int mi = 0; mi < 2; mi++){
                int row = mi*16 + (lane & 15);
                int kc  = ks + (lane >> 4)*8;
                ldsmx4(ah[mi], pA0 + row*SLD3 + kc);
                ldsmx4(al[mi], pA1 + row*SLD3 + kc);
            }
            {
                int l = lane & 15;
                int row = q*8 + (l & 7);
                int kc  = ks + ((l >> 3) & 1)*8;
                ldsmx2(bh, pB0 + row*SLD3 + kc);
                ldsmx2(bl, pB1 + row*SLD3 + kc);
            }
#pragma unroll
            for (int mi = 0; mi < 2; mi++){
                mma_bf(acc[mi], ah[mi], bh);
                mma_bf(acc[mi], ah[mi], bl);
                mma_bf(acc[mi], al[mi], bh);
            }
        }
    }
    // scatter partials: [half][quadrant]
#pragma unroll
    for (int mi = 0; mi < 2; mi++)
#pragma unroll
    for (int h = 0; h < 2; h++){
        int b  = mi*16 + (lane >> 2) + h*8;
        int jl = (lane & 3)*2;
        sG[half][q][b][jl]   = acc[mi][h*2];
        sG[half][q][b][jl+1] = acc[mi][h*2+1];
    }
    __syncthreads();
    // LSTM cell update: one element per thread (32x8 = 256)
    bf16* oHi = g_H_hi + (size_t)(s+1)*Bz*Gz;
    bf16* oLo = g_H_lo + (size_t)(s+1)*Bz*Gz;
    __half* fHi = g_Hf_hi + (size_t)(s+1)*Bz*Gz;
    const float* Xg = g_Xg + (size_t)s*Bz*G4z;
    {
        int b = tid >> 3, jl = tid & 7;
        int col = c0 + jl;
        const float* xg = Xg + (size_t)b*G4z;
        float gi = sG[0][0][b][jl] + sG[1][0][b][jl] + xg[col];
        float gf = sG[0][1][b][jl] + sG[1][1][b][jl] + xg[col +   Gz];
        float gg = sG[0][2][b][jl] + sG[1][2][b][jl] + xg[col + 2*Gz];
        float go = sG[0][3][b][jl] + sG[1][3][b][jl] + xg[col + 3*Gz];
        float c = sigf(gf)*g_c[b*Gz+col] + sigf(gi)*tanhf(gg);
        float h = sigf(go)*tanhf(c);
        g_c[b*Gz+col] = c;
        bf16 hb = __float2bfloat16(h);
        oHi[b*Gz+col] = hb;
        oLo[b*Gz+col] = __float2bfloat16(h - __bfloat162float(hb));
        fHi[b*Gz+col] = __float2half(h);
    }
}

// ------ pipelined split-bf16 3-term GEMM (Xg + prologue), act 0/1=tanh ---
#define LDT   40
#define MATB  (128*LDT*2)
#define STGB  (4*MATB)
#define GEMM_SMEM (3*STGB)       /* 122880 */
__global__ void __launch_bounds__(256, 1) k_gemm3p(
    const bf16* __restrict__ Ahi, const bf16* __restrict__ Alo,
    const bf16* __restrict__ Bhi, const bf16* __restrict__ Blo,
    const float* __restrict__ bias, float* __restrict__ out,
    int M, int N, int K, int act)
{
    extern __shared__ char smem[];
    const uint32_t sb = smem_u32(smem);
    const int tid = threadIdx.x, warp = tid >> 5, lane = tid & 31;
    const int m0 = blockIdx.x*128, n0 = blockIdx.y*128;
    const int wm = (warp >> 2)*64, wn = (warp & 3)*32;
    const int NC = K >> 5;

    float acc[4][4][4];
#pragma unroll
    for (int a=0;a<4;a++)
#pragma unroll
    for (int b=0;b<4;b++)
#pragma unroll
    for (int c=0;c<4;c++) acc[a][b][c]=0.f;

    auto load_stage = [&](int chunk, int buf){
        const int kk = chunk << 5;
        const uint32_t s0 = sb + buf*STGB;
#pragma unroll
        for (int i = 0; i < 2; i++){
            int u = tid + i*256;
            int r = u >> 2, c = (u & 3)*8;
            uint32_t so = (uint32_t)((r*LDT + c)*2);
            int gr = m0 + r;
            uint32_t pv = (gr < M) ? 16u : 0u;
            int grc = gr < M ? gr : (M-1);
            CP_ASYNC16P(s0 + so,          Ahi + (size_t)grc*K + kk + c, pv);
            CP_ASYNC16P(s0 + MATB + so,   Alo + (size_t)grc*K + kk + c, pv);
            int gn = n0 + r;
            CP_ASYNC16(s0 + 2*MATB + so,  Bhi + (size_t)gn*K + kk + c);
            CP_ASYNC16(s0 + 3*MATB + so,  Blo + (size_t)gn*K + kk + c);
        }
    };
    load_stage(0, 0); CP_COMMIT();
    if (NC > 1){ load_stage(1, 1); } CP_COMMIT();

    for (int c = 0; c < NC; c++){
        asm volatile("cp.async.wait_group 1;" ::: "memory");
        __syncthreads();
        if (c + 2 < NC) load_stage(c + 2, (c + 2) % 3);
        CP_COMMIT();
        const char* st = smem + (c % 3)*STGB;
        const bf16* pA0 = (const bf16*)(st);
        const bf16* pA1 = (const bf16*)(st + MATB);
        const bf16* pB0 = (const bf16*)(st + 2*MATB);
        const bf16* pB1 = (const bf16*)(st + 3*MATB);
#pragma unroll
        for (int ks = 0; ks < 32; ks += 16){
            uint32_t ah[4][4], al[4][4], bh[2][4], bl[2][4];
#pragma unroll
            for (int mi = 0; mi < 4; mi++){
                int row = wm + mi*16 + (lane & 15);
                int kc  = ks + (lane >> 4)*8;
                ldsmx4(ah[mi], pA0 + row*LDT + kc);
                ldsmx4(al[mi], pA1 + row*LDT + kc);
            }
#pragma unroll
            for (int ni = 0; ni < 2; ni++){
                int j = lane >> 3;
                int row = wn + ni*16 + ((j >> 1)*8) + (lane & 7);
                int kc  = ks + (j & 1)*8;
                ldsmx4(bh[ni], pB0 + row*LDT + kc);
                ldsmx4(bl[ni], pB1 + row*LDT + kc);
            }
#pragma unroll
            for (int mi = 0; mi < 4; mi++)
#pragma unroll
                for (int nj = 0; nj < 4; nj++){
                    const uint32_t* fh = &bh[nj >> 1][(nj & 1)*2];
                    const uint32_t* fl = &bl[nj >> 1][(nj & 1)*2];
                    mma_bf(acc[mi][nj], ah[mi], fh);
                    mma_bf(acc[mi][nj], ah[mi], fl);
                    mma_bf(acc[mi][nj], al[mi], fh);
                }
        }
    }
#pragma unroll
    for (int mi = 0; mi < 4; mi++)
#pragma unroll
    for (int nj = 0; nj < 4; nj++){
        int n = n0 + wn + nj*8 + (lane & 3)*2;
        float b0 = bias[n], b1 = bias[n+1];
#pragma unroll
        for (int h = 0; h < 2; h++){
            int m = m0 + wm + mi*16 + (lane >> 2) + h*8;
            if (m < M){
                float v0 = acc[mi][nj][h*2]   + b0;
                float v1 = acc[mi][nj][h*2+1] + b1;
                if (act == 1){ v0 = tanhf(v0); v1 = tanhf(v1); }
                out[(size_t)m*N + n]   = v0;
                out[(size_t)m*N + n+1] = v1;
            }
        }
    }
}

// ---- logits: fp16 1-term GEMM, BK=64, 2-stage, 2 CTAs/SM ----------------
// remap: row m = t*32+b  ->  out[(b*127+t)*Vz + n]
#define LDTL  72
#define MATL  (128*LDTL*2)       /* 18432 */
#define STGL  (2*MATL)           /* Ah, Bh = 36864 */
#define LOG_SMEM (2*STGL)        /* 73728 -> 2 CTAs/SM */
__global__ void __launch_bounds__(256, 2) k_logits16(
    const __half* __restrict__ Ahi,
    const __half* __restrict__ Bhi,
    const float* __restrict__ bias, float* __restrict__ out,
    int M, int N, int K)
{
    extern __shared__ char smem[];
    const uint32_t sb = smem_u32(smem);
    const int tid = threadIdx.x, warp = tid >> 5, lane = tid & 31;
    const int m0 = blockIdx.x*128, n0 = blockIdx.y*128;
    const int wm = (warp >> 2)*64, wn = (warp & 3)*32;
    const int NC = K >> 6;       // chunks of 64

    float acc[4][4][4];
#pragma unroll
    for (int a=0;a<4;a++)
#pragma unroll
    for (int b=0;b<4;b++)
#pragma unroll
    for (int c=0;c<4;c++) acc[a][b][c]=0.f;

    auto load_stage = [&](int chunk, int buf){
        const int kk = chunk << 6;
        const uint32_t s0 = sb + buf*STGL;
#pragma unroll
        for (int i = 0; i < 4; i++){
            int u = tid + i*256;                 // 0..1023
            int r = u >> 3, c = (u & 7)*8;
            uint32_t so = (uint32_t)((r*LDTL + c)*2);
            int gr = m0 + r;
            uint32_t pv = (gr < M) ? 16u : 0u;
            int grc = gr < M ? gr : (M-1);
            CP_ASYNC16P(s0 + so,        Ahi + (size_t)grc*K + kk + c, pv);
            int gn = n0 + r;
            CP_ASYNC16(s0 + MATL + so,  Bhi + (size_t)gn*K + kk + c);
        }
    };
    load_stage(0, 0); CP_COMMIT();
    load_stage(1, 1); CP_COMMIT();

    for (int c = 0; c < NC; c++){
        asm volatile("cp.async.wait_group 1;" ::: "memory");
        __syncthreads();
        const char* st = smem + (c & 1)*STGL;
        const __half* pA0 = (const __half*)(st);
        const __half* pB0 = (const __half*)(st + MATL);
#pragma unroll
        for (int ks = 0; ks < 64; ks += 16){
            uint32_t ah[4][4], bh[2][4];
#pragma unroll
            for (int mi = 0; mi < 4; mi++){
                int row = wm + mi*16 + (lane & 15);
                int kc  = ks + (lane >> 4)*8;
                ldsmx4(ah[mi], pA0 + row*LDTL + kc);
            }
#pragma unroll
            for (int ni = 0; ni < 2; ni++){
                int j = lane >> 3;
                int row = wn + ni*16 + ((j >> 1)*8) + (lane & 7);
                int kc  = ks + (j & 1)*8;
                ldsmx4(bh[ni], pB0 + row*LDTL + kc);
            }
#pragma unroll
            for (int mi = 0; mi < 4; mi++)
#pragma unroll
                for (int nj = 0; nj < 4; nj++){
                    const uint32_t* fh = &bh[nj >> 1][(nj & 1)*2];
                    mma_fp(acc[mi][nj], ah[mi], fh);
                }
        }
        // all warps done consuming buf (c&1) before overwriting it
        __syncthreads();
        if (c + 2 < NC){ load_stage(c + 2, (c + 2) & 1); CP_COMMIT(); }
    }
#pragma unroll
    for (int mi = 0; mi < 4; mi++)
#pragma unroll
    for (int nj = 0; nj < 4; nj++){
        int n = n0 + wn + nj*8 + (lane & 3)*2;
        float b0 = bias[n], b1 = bias[n+1];
#pragma unroll
        for (int h = 0; h < 2; h++){
            int m = m0 + wm + mi*16 + (lane >> 2) + h*8;
            if (m < M){
                int t = m >> 5, b = m & 31;
                size_t off = ((size_t)b*Tz + t)*(size_t)N + n;
                out[off]   = acc[mi][nj][h*2]   + b0;
                out[off+1] = acc[mi][nj][h*2+1] + b1;
            }
        }
    }
}

// ------------------------------- tail ------------------------------------
__global__ void k_tail(const int* __restrict__ sent, const int* __restrict__ slen,
                       float* __restrict__ out, long out_size){
    long base = (long)Bz*Tz*Vz;
    int i = blockIdx.x*blockDim.x + threadIdx.x;
    if (i < Bz*Sz && base + i < out_size)            out[base+i] = (float)sent[i];
    if (i < Bz && base + Bz*Sz + i < out_size)       out[base+Bz*Sz+i] = (float)slen[i];
}

// ------------------------------ host side --------------------------------
static inline void* sym(const void* s){ void* p; cudaGetSymbolAddress(&p, s); return p; }

extern "C" void kernel_launch(void* const* d_in, const int* in_sizes, int n_in,
                              void* d_out, int out_size) {
    const float* ent   = (const float*)d_in[0];
    const float* neigh = (const float*)d_in[1];
    const int*   nnum  = (const int*)  d_in[2];
    const float* img   = (const float*)d_in[3];
    const int*   sent  = (const int*)  d_in[4];
    const int*   slen  = (const int*)  d_in[5];
    const float* emb   = (const float*)d_in[6];
    const float* W_ih  = (const float*)d_in[7];
    const float* W_hh  = (const float*)d_in[8];
    const float* b_ih  = (const float*)d_in[9];
    const float* b_hh  = (const float*)d_in[10];
    const float* W_img = (const float*)d_in[11];
    const float* b_img = (const float*)d_in[12];
    const float* W_out = (const float*)d_in[13];
    const float* b_out = (const float*)d_in[14];
    const float* Wq = (const float*)d_in[15]; const float* bq = (const float*)d_in[16];
    const float* Wk = (const float*)d_in[17]; const float* bk = (const float*)d_in[18];
    const float* Wv = (const float*)d_in[19]; const float* bv = (const float*)d_in[20];
    const float* Wo = (const float*)d_in[21]; const float* bo = (const float*)d_in[22];
    float* out = (float*)d_out;

    void *pWoutf = sym(g_Woutf);
    void *pWih_h = sym(g_Wih_hi), *pWih_l = sym(g_Wih_lo);
    void *pWhh_h = sym(g_Whh_hi), *pWhh_l = sym(g_Whh_lo);
    void *pHf_h = sym(g_Hf_hi);
    void *pXh = sym(g_X_hi), *pXl = sym(g_X_lo);
    void *pXg = sym(g_Xg), *pBsum = sym(g_bsum);
    void *pQ = sym(g_Q), *pKb = sym(g_Kb), *pVb = sym(g_Vb);
    void *pCtx = sym(g_ctx), *pAtt = sym(g_att), *pFf = sym(g_ff);
    void *pIe = sym(g_ie), *pG0 = sym(g_g0);
    void *pEnt_h = sym(g_ent_h), *pEnt_l = sym(g_ent_l);
    void *pNei_h = sym(g_nei_h), *pNei_l = sym(g_nei_l);
    void *pCtx_h = sym(g_ctx_h), *pCtx_l = sym(g_ctx_l);
    void *pFfs_h = sym(g_ffs_h), *pFfs_l = sym(g_ffs_l);
    void *pIe_h = sym(g_ie_h), *pIe_l = sym(g_ie_l);
    void *pWq_h = sym(g_Wq_h), *pWq_l = sym(g_Wq_l);
    void *pWk_h = sym(g_Wk_h), *pWk_l = sym(g_Wk_l);
    void *pWv_h = sym(g_Wv_h), *pWv_l = sym(g_Wv_l);
    void *pWo_h = sym(g_Wo_h), *pWo_l = sym(g_Wo_l);
    void *pWim_h = sym(g_Wim_h), *pWim_l = sym(g_Wim_l);

    cudaFuncSetAttribute(k_gemm3p,  cudaFuncAttributeMaxDynamicSharedMemorySize, GEMM_SMEM);
    cudaFuncSetAttribute(k_logits16,cudaFuncAttributeMaxDynamicSharedMemorySize, LOG_SMEM);
    cudaFuncSetAttribute(k_step,    cudaFuncAttributeMaxDynamicSharedMemorySize, STEP_SMEM);

    // ---- prep part 1 (ordered so launch #4 = Xg GEMM for ncu capture) ----
    {
        int n = G4z*Ez;
        k_split<<<(n+255)/256, 256>>>(W_ih, (bf16*)pWih_h, (bf16*)pWih_l, n);   // 1
        n = MR*Ez;
        k_xgather<<<(n+255)/256, 256>>>(emb, sent);                             // 2
        k_bsum<<<(G4z+255)/256, 256>>>(b_ih, b_hh);                             // 3
        dim3 grid((MR+127)/128, G4z/128);                                       // 4: Xg
        k_gemm3p<<<grid, 256, GEMM_SMEM>>>((bf16*)pXh, (bf16*)pXl,
                               (bf16*)pWih_h, (bf16*)pWih_l,
                               (const float*)pBsum, (float*)pXg,
                               MR, G4z, Ez, 0);
    }
    // ---- prep part 2 ----
    {
        int n = Vz*Gz;
        k_half<<<(n+255)/256, 256>>>(W_out, (__half*)pWoutf, n);
        n = G4z*Gz;
        k_split<<<(n+255)/256, 256>>>(W_hh, (bf16*)pWhh_h, (bf16*)pWhh_l, n);
        n = HIz*HIz;
        k_split<<<(n+255)/256, 256>>>(Wq, (bf16*)pWq_h, (bf16*)pWq_l, n);
        k_split<<<(n+255)/256, 256>>>(Wk, (bf16*)pWk_h, (bf16*)pWk_l, n);
        k_split<<<(n+255)/256, 256>>>(Wv, (bf16*)pWv_h, (bf16*)pWv_l, n);
        k_split<<<(n+255)/256, 256>>>(Wo, (bf16*)pWo_h, (bf16*)pWo_l, n);
        n = Ez*3*HIz;
        k_split<<<(n+255)/256, 256>>>(W_img, (bf16*)pWim_h, (bf16*)pWim_l, n);
        n = Bz*HIz;
        k_split<<<(n+255)/256, 256>>>(ent, (bf16*)pEnt_h, (bf16*)pEnt_l, n);
        n = Bz*16*HIz;
        k_split<<<(n+255)/256, 256>>>(neigh, (bf16*)pNei_h, (bf16*)pNei_l, n);
    }

    // ---- prologue: MHA + img_embed + first LSTM step (tensor-core GEMMs) ----
    {
        dim3 g1(1, HIz/128), g4(4, HIz/128);
        k_gemm3p<<<g1, 256, GEMM_SMEM>>>((bf16*)pEnt_h, (bf16*)pEnt_l,
            (bf16*)pWq_h, (bf16*)pWq_l, bq, (float*)pQ, Bz, HIz, HIz, 0);
        k_gemm3p<<<g4, 256, GEMM_SMEM>>>((bf16*)pNei_h, (bf16*)pNei_l,
            (bf16*)pWk_h, (bf16*)pWk_l, bk, (float*)pKb, Bz*16, HIz, HIz, 0);
        k_gemm3p<<<g4, 256, GEMM_SMEM>>>((bf16*)pNei_h, (bf16*)pNei_l,
            (bf16*)pWv_h, (bf16*)pWv_l, bv, (float*)pVb, Bz*16, HIz, HIz, 0);
        k_attn<<<Bz*8, 64>>>(nnum);
        int n = Bz*HIz;
        k_split<<<(n+255)/256, 256>>>((const float*)pCtx, (bf16*)pCtx_h, (bf16*)pCtx_l, n);
        k_gemm3p<<<g1, 256, GEMM_SMEM>>>((bf16*)pCtx_h, (bf16*)pCtx_l,
            (bf16*)pWo_h, (bf16*)pWo_l, bo, (float*)pAtt, Bz, HIz, HIz, 0);
        k_ff<<<(Bz*HIz+255)/256, 256>>>(ent, img);
        n = Bz*3*HIz;
        k_split<<<(n+255)/256, 256>>>((const float*)pFf, (bf16*)pFfs_h, (bf16*)pFfs_l, n);
        k_gemm3p<<<g1, 256, GEMM_SMEM>>>((bf16*)pFfs_h, (bf16*)pFfs_l,
            (bf16*)pWim_h, (bf16*)pWim_l, b_img, (float*)pIe, Bz, HIz, 3*HIz, 1);
        n = Bz*Ez;
        k_split<<<(n+255)/256, 256>>>((const float*)pIe, (bf16*)pIe_h, (bf16*)pIe_l, n);
        dim3 gg(1, G4z/128);
        k_gemm3p<<<gg, 256, GEMM_SMEM>>>((bf16*)pIe_h, (bf16*)pIe_l,
            (bf16*)pWih_h, (bf16*)pWih_l, (const float*)pBsum, (float*)pG0, Bz, G4z, Ez, 0);
        k_step0<<<(Bz*Gz+255)/256, 256>>>();
    }

    // ---- recurrence: 127 fused steps, 128 blocks x 256 thr ----
    for (int s = 0; s < Tz; s++)
        k_step<<<128, 256, STEP_SMEM>>>(s);

    // ---- logits: fp16 1-term BK=64, 2 CTAs/SM, remap [B,T,V] ----
    {
        dim3 grid((MR+127)/128, Vz/128);   // 32 x 250
        k_logits16<<<grid, 256, LOG_SMEM>>>(
            (const __half*)pHf_h + Bz*Gz,
            (const __half*)pWoutf, b_out, out, MR, Vz, Gz);
    }

    // ---- tuple tail ----
    if ((long)out_size > (long)Bz*Tz*Vz)
        k_tail<<<(Bz*Sz+255)/256, 256>>>(sent, slen, out, (long)out_size);
}